// round 6
// baseline (speedup 1.0000x reference)
#include <cuda_runtime.h>
#include <stdint.h>

// ---------------------------------------------------------------------------
// Problem constants
// ---------------------------------------------------------------------------
#define Vn   10000
#define NBAT 4
#define NTT  12
#define NN   96          // 2 branches * 4 * 12
#define NH   3
#define NE   512
#define NS   32
#define ES   (NE*NS)     // 16384

typedef unsigned long long u64;

// ---------------------------------------------------------------------------
// Device scratch (static allocation; no cudaMalloc allowed)
// ---------------------------------------------------------------------------
__device__ float g_Ft   [Vn * NN];        // transposed inputs F[v][n]
__device__ int   g_degi [NH * Vn];        // vertex degree per hypergraph
__device__ float g_rdeg [NH * Vn];        // 1 / max(deg,1)
__device__ float g_a1   [NH * NE * NN];   // layer-1 edge means
__device__ float g_s1   [NH * Vn * NN];   // layer-1 raw scatter sums
__device__ float g_m1   [NH * NE * NN];   // layer-2 edge means
__device__ float g_traw [NH * Vn * NN];   // layer-2 raw scatter sums
__device__ float g_T    [NN * Vn];        // attention-fused scalar field (t)
__device__ float g_P    [NN * Vn];        // attention-fused incidence field
__device__ float g_gc   [256];            // w_ih @ c
__device__ float g_gd   [256];            // w_ih @ d
__device__ float g_g0   [256];            // w_ih @ b2 + b_ih + b_hh
__device__ float g_whT  [64 * 256];       // w_hh re-laid-out [kin][kout][gate]
__device__ float g_sc   [6];              // CT, DT, BT, CB, DB, BB

// ---------------------------------------------------------------------------
// f32x2 packed-math helpers (FFMA2: 2x fp32 FMA per issue slot)
// ---------------------------------------------------------------------------
__device__ __forceinline__ void fma2(u64& d, u64 a, u64 b) {
    asm("fma.rn.f32x2 %0, %1, %2, %0;" : "+l"(d) : "l"(a), "l"(b));
}
__device__ __forceinline__ u64 splat2(float x) {
    u64 r; unsigned u = __float_as_uint(x);
    asm("mov.b64 %0, {%1, %1};" : "=l"(r) : "r"(u));
    return r;
}
__device__ __forceinline__ float2 unpk(u64 a) {
    unsigned lo, hi;
    asm("mov.b64 {%0, %1}, %2;" : "=r"(lo), "=r"(hi) : "l"(a));
    return make_float2(__uint_as_float(lo), __uint_as_float(hi));
}

__device__ __forceinline__ float sigm(float x) {
    float t = __expf(-x);
    return __fdividef(1.0f, 1.0f + t);
}
__device__ __forceinline__ float tanh_e(float x) {
    x = fminf(fmaxf(x, -8.0f), 8.0f);
    float t = __expf(2.0f * x);
    return __fdividef(t - 1.0f, t + 1.0f);
}

// ---------------------------------------------------------------------------
// Kernel 0: zero scratch + init output to b_out
// ---------------------------------------------------------------------------
__global__ void k_zero(float* __restrict__ out, const float* __restrict__ b_out) {
    int i = blockIdx.x * 256 + threadIdx.x;   // grid covers NH*Vn*NN = 2,880,000
    g_s1[i]   = 0.f;
    g_traw[i] = 0.f;
    if (i < NH * Vn) g_degi[i] = 0;
    if (i < NBAT * Vn) out[i] = b_out[0];
}

// ---------------------------------------------------------------------------
// Kernel 1: precompute weight-derived constants (1 block, 256 threads)
// ---------------------------------------------------------------------------
__global__ void k_prep(const float* __restrict__ w1,     const float* __restrict__ b1,
                       const float* __restrict__ w2,     const float* __restrict__ b2,
                       const float* __restrict__ attn_w, const float* __restrict__ attn_a,
                       const float* __restrict__ w_ih,   const float* __restrict__ w_hh,
                       const float* __restrict__ b_ih,   const float* __restrict__ b_hh) {
    __shared__ float csh[64], dsh[64], cw[64], dw[64], bw[64];
    int t = threadIdx.x;

    if (t < 64) {
        float c = 0.f, d = 0.f;
        for (int i = 0; i < 64; i++) {
            float w = w2[i * 64 + t];
            c += w1[i] * w;
            d += b1[i] * w;
        }
        csh[t] = c; dsh[t] = d;
    }
    __syncthreads();

    if (t < 64) {
        float a = 0.f, b = 0.f, c = 0.f;
        for (int i = 0; i < 64; i++) {
            float w = attn_w[i * 64 + t];
            a += csh[i] * w;
            b += dsh[i] * w;
            c += b2[i]  * w;
        }
        cw[t] = a; dw[t] = b; bw[t] = c;
    }
    __syncthreads();

    if (t == 0) {
        float CT=0,DT=0,BT=0,CB=0,DB=0,BB=0;
        for (int j = 0; j < 64; j++) {
            float at = attn_a[j], ab = attn_a[64 + j];
            CT += cw[j]*at; DT += dw[j]*at; BT += bw[j]*at;
            CB += cw[j]*ab; DB += dw[j]*ab; BB += bw[j]*ab;
        }
        g_sc[0]=CT; g_sc[1]=DT; g_sc[2]=BT; g_sc[3]=CB; g_sc[4]=DB; g_sc[5]=BB;
    }

    // gc/gd/g0 for LSTM input projection (t in [0,256))
    {
        float a = 0.f, b = 0.f, c = 0.f;
        for (int k = 0; k < 64; k++) {
            float w = w_ih[t * 64 + k];
            a += w * csh[k];
            b += w * dsh[k];
            c += w * b2[k];
        }
        g_gc[t] = a;
        g_gd[t] = b;
        g_g0[t] = c + b_ih[t] + b_hh[t];
    }

    // Re-layout w_hh -> whT[kin*256 + kout*4 + gate] = w_hh[(gate*64+kout)*64 + kin]
    for (int idx = t; idx < 16384; idx += 256) {
        int kin = idx >> 8, r = idx & 255, kout = r >> 2, g = r & 3;
        g_whT[idx] = w_hh[(g * 64 + kout) * 64 + kin];
    }
}

// ---------------------------------------------------------------------------
// Kernel 2: transpose inputs into F[v][n]  (n = branch*48 + b*12 + t)
// ---------------------------------------------------------------------------
__global__ void k_transpose(const float* __restrict__ ten, const float* __restrict__ per) {
    int i = blockIdx.x * 256 + threadIdx.x;   // < Vn*NN
    int v = i / NN, n = i % NN;
    const float* src = (n < 48) ? ten : per;
    int nl = n % 48;
    g_Ft[i] = src[nl * Vn + v];
}

// ---------------------------------------------------------------------------
// Kernel 3: vertex degree per hypergraph
// ---------------------------------------------------------------------------
__global__ void k_deg(const int* __restrict__ edges) {
    int i = blockIdx.x * 256 + threadIdx.x;   // < NH*ES
    int h = i / ES;
    atomicAdd(&g_degi[h * Vn + edges[i]], 1);
}

__global__ void k_rdeg() {
    int i = blockIdx.x * 256 + threadIdx.x;
    if (i < NH * Vn) {
        int dg = g_degi[i];
        g_rdeg[i] = 1.0f / (float)(dg > 0 ? dg : 1);
    }
}

// ---------------------------------------------------------------------------
// Kernel 4: a1[h][e][n] = mean_s F[edges[h,e,s]][n]   (float4 over n)
// ---------------------------------------------------------------------------
__global__ void k_gather_a1(const int* __restrict__ edges) {
    int i = blockIdx.x * 256 + threadIdx.x;   // < NH*NE*24
    int n4 = (i % 24) * 4;
    int e  = (i / 24) % NE;
    int h  = i / (24 * NE);
    const int* ep = edges + (h * NE + e) * NS;
    float4 acc = make_float4(0.f, 0.f, 0.f, 0.f);
    #pragma unroll
    for (int s = 0; s < NS; s++) {
        const float4 f = *(const float4*)&g_Ft[ep[s] * NN + n4];
        acc.x += f.x; acc.y += f.y; acc.z += f.z; acc.w += f.w;
    }
    const float r = 1.0f / NS;
    acc.x *= r; acc.y *= r; acc.z *= r; acc.w *= r;
    *(float4*)&g_a1[(h * NE + e) * NN + n4] = acc;
}

// ---------------------------------------------------------------------------
// Kernel 5: scatter a1 -> s1 raw sums (vectorized red.global.add.v4.f32)
// ---------------------------------------------------------------------------
__device__ __forceinline__ void red_v4(float* p, float4 v) {
    asm volatile("red.global.add.v4.f32 [%0], {%1, %2, %3, %4};"
                 :: "l"(p), "f"(v.x), "f"(v.y), "f"(v.z), "f"(v.w) : "memory");
}

__global__ void k_scatter_s1(const int* __restrict__ edges) {
    int i = blockIdx.x * 256 + threadIdx.x;   // < NH*ES*24
    int n4   = (i % 24) * 4;
    int slot = (i / 24) % ES;
    int h    = i / (24 * ES);
    int v = edges[h * ES + slot];
    int e = slot >> 5;
    float4 a = *(const float4*)&g_a1[(h * NE + e) * NN + n4];
    red_v4(&g_s1[(h * Vn + v) * NN + n4], a);
}

// ---------------------------------------------------------------------------
// Kernel 6: m1[h][e][n] = mean_s ( s1[edges]/deg )
// ---------------------------------------------------------------------------
__global__ void k_gather_m1(const int* __restrict__ edges) {
    int i = blockIdx.x * 256 + threadIdx.x;   // < NH*NE*24
    int n4 = (i % 24) * 4;
    int e  = (i / 24) % NE;
    int h  = i / (24 * NE);
    const int* ep = edges + (h * NE + e) * NS;
    float4 acc = make_float4(0.f, 0.f, 0.f, 0.f);
    #pragma unroll
    for (int s = 0; s < NS; s++) {
        int v = ep[s];
        float rd = g_rdeg[h * Vn + v];
        const float4 f = *(const float4*)&g_s1[(h * Vn + v) * NN + n4];
        acc.x += f.x * rd; acc.y += f.y * rd; acc.z += f.z * rd; acc.w += f.w * rd;
    }
    const float r = 1.0f / NS;
    acc.x *= r; acc.y *= r; acc.z *= r; acc.w *= r;
    *(float4*)&g_m1[(h * NE + e) * NN + n4] = acc;
}

// ---------------------------------------------------------------------------
// Kernel 7: scatter m1 -> traw
// ---------------------------------------------------------------------------
__global__ void k_scatter_t(const int* __restrict__ edges) {
    int i = blockIdx.x * 256 + threadIdx.x;   // < NH*ES*24
    int n4   = (i % 24) * 4;
    int slot = (i / 24) % ES;
    int h    = i / (24 * ES);
    int v = edges[h * ES + slot];
    int e = slot >> 5;
    float4 a = *(const float4*)&g_m1[(h * NE + e) * NN + n4];
    red_v4(&g_traw[(h * Vn + v) * NN + n4], a);
}

// ---------------------------------------------------------------------------
// Kernel 8: attention over H=3 (scalar form) -> T, P fields
// ---------------------------------------------------------------------------
__global__ void k_attn() {
    int i = blockIdx.x * 256 + threadIdx.x;   // < NN*Vn, layout [n][v]
    int v = i % Vn;
    int n = i / Vn;

    float CT = g_sc[0], DT = g_sc[1], BT = g_sc[2];
    float CB = g_sc[3], DB = g_sc[4], BB = g_sc[5];

    float tv[NH], uf[NH];
    #pragma unroll
    for (int h = 0; h < NH; h++) {
        int idx = h * Vn + v;
        int dg = g_degi[idx];
        uf[h] = (dg > 0) ? 1.0f : 0.0f;
        tv[h] = g_traw[idx * NN + n] * g_rdeg[idx];
    }
    float tbar = (tv[0] + tv[1] + tv[2]) * (1.0f / 3.0f);
    float usum = uf[0] + uf[1] + uf[2];
    float zc = CB * tbar + BB + usum * (1.0f / 3.0f) * DB;

    float z[NH];
    #pragma unroll
    for (int h = 0; h < NH; h++) {
        float zz = CT * tv[h] + uf[h] * DT + BT + zc;
        z[h] = (zz > 0.f) ? zz : 0.2f * zz;     // leaky_relu(0.2)
    }
    float m = fmaxf(z[0], fmaxf(z[1], z[2]));
    float e0 = __expf(z[0] - m), e1 = __expf(z[1] - m), e2 = __expf(z[2] - m);
    float rden = 1.0f / (e0 + e1 + e2);
    g_T[i] = (e0 * tv[0] + e1 * tv[1] + e2 * tv[2]) * rden;
    g_P[i] = (e0 * uf[0] + e1 * uf[1] + e2 * uf[2]) * rden;
}

// ---------------------------------------------------------------------------
// Kernel 9: LSTM over 80000 independent sequences + final projection
//   block = 64 sequences, 256 threads
//   thread tile: 8 sequences x (2 k-outputs x 4 gates), packed f32x2 math
//   h stored duplicated in shared ((h,h) pairs) so FFMA2 needs no splats
//   NOTE: no minBlocksPerMultiprocessor — smem (106 KB) forces 1 CTA/SM
//   anyway, and capping regs at 128 caused catastrophic spills in R4.
// ---------------------------------------------------------------------------
#define HS2 132                       // padded row stride of hsh2 (floats)

// smem layout (floats):
//  wsh   [0,16384)         w_hh [kin][kout*4+gate]
//  hsh2  [16384, +64*132)  h duplicated: row kin, col 2s/2s+1
//  Tsh   [24832, +768)
//  Psh   [25600, +768)
//  gcsh  [26368, +256)
//  gdsh  [26624, +256)
//  g0sh  [26880, +256)
//  outsh [27136, +64)
#define SM_WSH   0
#define SM_HSH2  16384
#define SM_TSH   24832
#define SM_PSH   25600
#define SM_GC    26368
#define SM_GD    26624
#define SM_G0    26880
#define SM_OUT   27136
#define SM_TOTAL 27200                // floats -> 108800 bytes

extern __shared__ float smem[];

__global__ void __launch_bounds__(256) k_lstm(const float* __restrict__ w_out,
                                              float* __restrict__ out) {
    float* wsh   = smem + SM_WSH;
    float* hsh2  = smem + SM_HSH2;
    float* Tsh   = smem + SM_TSH;
    float* Psh   = smem + SM_PSH;
    float* gcsh  = smem + SM_GC;
    float* gdsh  = smem + SM_GD;
    float* g0sh  = smem + SM_G0;
    float* outsh = smem + SM_OUT;

    int tid = threadIdx.x;
    int st  = tid & 7;        // seq group: seqs st*8 .. st*8+7
    int kt  = tid >> 3;       // 0..31
    int k0  = kt * 2;         // output k pair
    int sb  = blockIdx.x * 64;

    // load shared
    for (int idx = tid * 4; idx < 16384; idx += 1024)
        *(float4*)&wsh[idx] = *(const float4*)&g_whT[idx];
    {
        int kout = tid >> 2, g = tid & 3;
        gcsh[tid] = g_gc[g * 64 + kout];
        gdsh[tid] = g_gd[g * 64 + kout];
        g0sh[tid] = g_g0[g * 64 + kout];
    }
    if (tid < 64) outsh[tid] = 0.f;
    for (int idx = tid; idx < 768; idx += 256) {
        int s = idx & 63, t = idx >> 6;
        int sid = sb + s;
        int branch = sid / 40000;
        int rem = sid - branch * 40000;
        int b = rem / Vn;
        int v = rem - b * Vn;
        int n = branch * 48 + b * 12 + t;
        Tsh[t * 64 + s] = g_T[n * Vn + v];
        Psh[t * 64 + s] = g_P[n * Vn + v];
    }
    __syncthreads();

    float cst[8][2];
    #pragma unroll
    for (int ss = 0; ss < 8; ss++) { cst[ss][0] = 0.f; cst[ss][1] = 0.f; }

    for (int t = 0; t < NTT; t++) {
        // input-projection init (packed pairs over adjacent gates)
        u64 acc[8][4];
        {
            ulonglong2 gcA = *(const ulonglong2*)&gcsh[k0 * 4];
            ulonglong2 gcB = *(const ulonglong2*)&gcsh[k0 * 4 + 4];
            ulonglong2 gdA = *(const ulonglong2*)&gdsh[k0 * 4];
            ulonglong2 gdB = *(const ulonglong2*)&gdsh[k0 * 4 + 4];
            ulonglong2 g0A = *(const ulonglong2*)&g0sh[k0 * 4];
            ulonglong2 g0B = *(const ulonglong2*)&g0sh[k0 * 4 + 4];
            u64 gcp[4] = {gcA.x, gcA.y, gcB.x, gcB.y};
            u64 gdp[4] = {gdA.x, gdA.y, gdB.x, gdB.y};
            u64 g0p[4] = {g0A.x, g0A.y, g0B.x, g0B.y};
            #pragma unroll
            for (int ss = 0; ss < 8; ss++) {
                float Tt = Tsh[t * 64 + st * 8 + ss];
                float Pt = Psh[t * 64 + st * 8 + ss];
                u64 Td = splat2(Tt), Pd = splat2(Pt);
                #pragma unroll
                for (int p = 0; p < 4; p++) {
                    acc[ss][p] = g0p[p];
                    fma2(acc[ss][p], Td, gcp[p]);
                    fma2(acc[ss][p], Pd, gdp[p]);
                }
            }
        }

        if (t > 0) {
            #pragma unroll 2
            for (int kin = 0; kin < 64; kin++) {
                const float* hrow = &hsh2[kin * HS2 + st * 16];
                ulonglong2 hA = *(const ulonglong2*)(hrow);
                ulonglong2 hB = *(const ulonglong2*)(hrow + 4);
                ulonglong2 hC = *(const ulonglong2*)(hrow + 8);
                ulonglong2 hD = *(const ulonglong2*)(hrow + 12);
                const float* wrow = &wsh[kin * 256 + k0 * 4];
                ulonglong2 wA = *(const ulonglong2*)(wrow);
                ulonglong2 wB = *(const ulonglong2*)(wrow + 4);
                // seqs 0,1 with hA
                fma2(acc[0][0], hA.x, wA.x); fma2(acc[0][1], hA.x, wA.y);
                fma2(acc[0][2], hA.x, wB.x); fma2(acc[0][3], hA.x, wB.y);
                fma2(acc[1][0], hA.y, wA.x); fma2(acc[1][1], hA.y, wA.y);
                fma2(acc[1][2], hA.y, wB.x); fma2(acc[1][3], hA.y, wB.y);
                // seqs 2,3 with hB
                fma2(acc[2][0], hB.x, wA.x); fma2(acc[2][1], hB.x, wA.y);
                fma2(acc[2][2], hB.x, wB.x); fma2(acc[2][3], hB.x, wB.y);
                fma2(acc[3][0], hB.y, wA.x); fma2(acc[3][1], hB.y, wA.y);
                fma2(acc[3][2], hB.y, wB.x); fma2(acc[3][3], hB.y, wB.y);
                // seqs 4,5 with hC
                fma2(acc[4][0], hC.x, wA.x); fma2(acc[4][1], hC.x, wA.y);
                fma2(acc[4][2], hC.x, wB.x); fma2(acc[4][3], hC.x, wB.y);
                fma2(acc[5][0], hC.y, wA.x); fma2(acc[5][1], hC.y, wA.y);
                fma2(acc[5][2], hC.y, wB.x); fma2(acc[5][3], hC.y, wB.y);
                // seqs 6,7 with hD
                fma2(acc[6][0], hD.x, wA.x); fma2(acc[6][1], hD.x, wA.y);
                fma2(acc[6][2], hD.x, wB.x); fma2(acc[6][3], hD.x, wB.y);
                fma2(acc[7][0], hD.y, wA.x); fma2(acc[7][1], hD.y, wA.y);
                fma2(acc[7][2], hD.y, wB.x); fma2(acc[7][3], hD.y, wB.y);
            }
        }
        __syncthreads();   // all hsh2 reads done before rewrite

        #pragma unroll
        for (int ss = 0; ss < 8; ss++) {
            #pragma unroll
            for (int kk = 0; kk < 2; kk++) {
                float2 a0 = unpk(acc[ss][kk * 2 + 0]);   // (gi, gf)
                float2 a1 = unpk(acc[ss][kk * 2 + 1]);   // (gg, go)
                float cn = sigm(a0.y) * cst[ss][kk] + sigm(a0.x) * tanh_e(a1.x);
                cst[ss][kk] = cn;
                float hn = sigm(a1.y) * tanh_e(cn);
                *(u64*)&hsh2[(k0 + kk) * HS2 + (st * 8 + ss) * 2] = splat2(hn);
            }
        }
        __syncthreads();   // new h visible
    }

    // final projection: out[b*V+v] += h . w_out[branch*64 : +64]
    int branch = sb / 40000;               // uniform per block (40000 % 64 == 0)
    float wo0 = w_out[branch * 64 + k0];
    float wo1 = w_out[branch * 64 + k0 + 1];
    #pragma unroll
    for (int ss = 0; ss < 8; ss++) {
        int s = st * 8 + ss;
        float p = hsh2[k0 * HS2 + 2 * s] * wo0 + hsh2[(k0 + 1) * HS2 + 2 * s] * wo1;
        atomicAdd(&outsh[s], p);
    }
    __syncthreads();
    if (tid < 64) {
        int sid = sb + tid;
        int rem = sid % 40000;             // = b*V + v
        atomicAdd(&out[rem], outsh[tid]);
    }
}

// ---------------------------------------------------------------------------
// Host launch
// ---------------------------------------------------------------------------
extern "C" void kernel_launch(void* const* d_in, const int* in_sizes, int n_in,
                              void* d_out, int out_size) {
    const float* tendency    = (const float*)d_in[0];
    const float* periodicity = (const float*)d_in[1];
    const int*   edges       = (const int*)  d_in[2];
    const float* w1          = (const float*)d_in[3];
    const float* b1          = (const float*)d_in[4];
    const float* w2          = (const float*)d_in[5];
    const float* b2          = (const float*)d_in[6];
    const float* attn_w      = (const float*)d_in[7];
    const float* attn_a      = (const float*)d_in[8];
    const float* w_ih        = (const float*)d_in[9];
    const float* w_hh        = (const float*)d_in[10];
    const float* b_ih        = (const float*)d_in[11];
    const float* b_hh        = (const float*)d_in[12];
    const float* w_out       = (const float*)d_in[13];
    const float* b_out       = (const float*)d_in[14];
    float* out = (float*)d_out;

    cudaFuncSetAttribute(k_lstm, cudaFuncAttributeMaxDynamicSharedMemorySize,
                         SM_TOTAL * 4);

    k_zero      <<<11250, 256>>>(out, b_out);
    k_prep      <<<1,     256>>>(w1, b1, w2, b2, attn_w, attn_a, w_ih, w_hh, b_ih, b_hh);
    k_transpose <<<3750,  256>>>(tendency, periodicity);
    k_deg       <<<(NH * ES) / 256, 256>>>(edges);            // 192 blocks
    k_rdeg      <<<(NH * Vn + 255) / 256, 256>>>();
    k_gather_a1 <<<(NH * NE * 24) / 256, 256>>>(edges);       // 144
    k_scatter_s1<<<(NH * ES * 24) / 256, 256>>>(edges);       // 4608
    k_gather_m1 <<<(NH * NE * 24) / 256, 256>>>(edges);
    k_scatter_t <<<(NH * ES * 24) / 256, 256>>>(edges);
    k_attn      <<<3750,  256>>>();
    k_lstm      <<<1250,  256, SM_TOTAL * 4>>>(w_out, out);
}

// round 12
// speedup vs baseline: 4.4425x; 4.4425x over previous
#include <cuda_runtime.h>
#include <cuda_bf16.h>
#include <stdint.h>

// ---------------------------------------------------------------------------
// Problem constants
// ---------------------------------------------------------------------------
#define Vn   10000
#define NBAT 4
#define NTT  12
#define NN   96          // 2 branches * 4 * 12
#define NH   3
#define NE   512
#define NS   32
#define ES   (NE*NS)     // 16384

typedef unsigned long long u64;

// ---------------------------------------------------------------------------
// Device scratch (static allocation; no cudaMalloc allowed)
// ---------------------------------------------------------------------------
__device__ float g_Ft   [Vn * NN];        // transposed inputs F[v][n]
__device__ int   g_degi [NH * Vn];        // vertex degree per hypergraph
__device__ float g_rdeg [NH * Vn];        // 1 / max(deg,1)
__device__ float g_a1   [NH * NE * NN];   // layer-1 edge means
__device__ float g_s1   [NH * Vn * NN];   // layer-1 raw scatter sums
__device__ float g_m1   [NH * NE * NN];   // layer-2 edge means
__device__ float g_traw [NH * Vn * NN];   // layer-2 raw scatter sums
__device__ float g_T    [NN * Vn];        // attention-fused scalar field (t)
__device__ float g_P    [NN * Vn];        // attention-fused incidence field
__device__ float g_gc   [256];            // w_ih @ c   [gate*64+kout]
__device__ float g_gd   [256];            // w_ih @ d
__device__ float g_g0   [256];            // w_ih @ b2 + b_ih + b_hh
__device__ float g_sc   [6];              // CT, DT, BT, CB, DB, BB
// W_hh mma B-fragments, per-lane register layout:
// index ((w*4 + tau)*4 + kt)*32 + lane -> {bhi0, bhi1, blo0, blo1}
__device__ uint4 g_Bfrag[8 * 4 * 4 * 32];

// ---------------------------------------------------------------------------
// Math helpers (fp32, exp-based — proven 1e-7 accurate in R3)
// ---------------------------------------------------------------------------
__device__ __forceinline__ float sigm(float x) {
    float t = __expf(-x);
    return __fdividef(1.0f, 1.0f + t);
}
__device__ __forceinline__ float tanh_e(float x) {
    x = fminf(fmaxf(x, -8.0f), 8.0f);
    float t = __expf(2.0f * x);
    return __fdividef(t - 1.0f, t + 1.0f);
}

__device__ __forceinline__ uint32_t smem_u32(const void* p) {
    uint32_t a;
    asm("{ .reg .u64 t; cvta.to.shared.u64 t, %1; cvt.u32.u64 %0, t; }"
        : "=r"(a) : "l"(p));
    return a;
}

// classic warp-level bf16 MMA, fp32 accumulate (sm_80+, works on plain sm_103)
__device__ __forceinline__ void mma_bf16(float* d, const uint32_t* a, const uint32_t* b) {
    asm volatile("mma.sync.aligned.m16n8k16.row.col.f32.bf16.bf16.f32 "
        "{%0,%1,%2,%3}, {%4,%5,%6,%7}, {%8,%9}, {%0,%1,%2,%3};"
        : "+f"(d[0]), "+f"(d[1]), "+f"(d[2]), "+f"(d[3])
        : "r"(a[0]), "r"(a[1]), "r"(a[2]), "r"(a[3]), "r"(b[0]), "r"(b[1]));
}
__device__ __forceinline__ void ldsm4(uint32_t* r, uint32_t addr) {
    asm volatile("ldmatrix.sync.aligned.m8n8.x4.shared.b16 {%0,%1,%2,%3}, [%4];"
        : "=r"(r[0]), "=r"(r[1]), "=r"(r[2]), "=r"(r[3]) : "r"(addr));
}

// ---------------------------------------------------------------------------
// Kernel 0: zero scratch + init output to b_out
// ---------------------------------------------------------------------------
__global__ void k_zero(float* __restrict__ out, const float* __restrict__ b_out) {
    int i = blockIdx.x * 256 + threadIdx.x;   // grid covers NH*Vn*NN = 2,880,000
    g_s1[i]   = 0.f;
    g_traw[i] = 0.f;
    if (i < NH * Vn) g_degi[i] = 0;
    if (i < NBAT * Vn) out[i] = b_out[0];
}

// ---------------------------------------------------------------------------
// Kernel 1: precompute weight-derived constants (1 block, 256 threads)
// ---------------------------------------------------------------------------
__device__ __forceinline__ uint32_t pack_bf2(float a, float b) {
    __nv_bfloat162 p = make_bfloat162(__float2bfloat16_rn(a), __float2bfloat16_rn(b));
    return *(uint32_t*)&p;
}

__global__ void k_prep(const float* __restrict__ w1,     const float* __restrict__ b1,
                       const float* __restrict__ w2,     const float* __restrict__ b2,
                       const float* __restrict__ attn_w, const float* __restrict__ attn_a,
                       const float* __restrict__ w_ih,   const float* __restrict__ w_hh,
                       const float* __restrict__ b_ih,   const float* __restrict__ b_hh) {
    __shared__ float csh[64], dsh[64], cw[64], dw[64], bw[64];
    int t = threadIdx.x;

    if (t < 64) {
        float c = 0.f, d = 0.f;
        for (int i = 0; i < 64; i++) {
            float w = w2[i * 64 + t];
            c += w1[i] * w;
            d += b1[i] * w;
        }
        csh[t] = c; dsh[t] = d;
    }
    __syncthreads();

    if (t < 64) {
        float a = 0.f, b = 0.f, c = 0.f;
        for (int i = 0; i < 64; i++) {
            float w = attn_w[i * 64 + t];
            a += csh[i] * w;
            b += dsh[i] * w;
            c += b2[i]  * w;
        }
        cw[t] = a; dw[t] = b; bw[t] = c;
    }
    __syncthreads();

    if (t == 0) {
        float CT=0,DT=0,BT=0,CB=0,DB=0,BB=0;
        for (int j = 0; j < 64; j++) {
            float at = attn_a[j], ab = attn_a[64 + j];
            CT += cw[j]*at; DT += dw[j]*at; BT += bw[j]*at;
            CB += cw[j]*ab; DB += dw[j]*ab; BB += bw[j]*ab;
        }
        g_sc[0]=CT; g_sc[1]=DT; g_sc[2]=BT; g_sc[3]=CB; g_sc[4]=DB; g_sc[5]=BB;
    }

    // gc/gd/g0 for LSTM input projection, layout [gate*64+kout]
    {
        float a = 0.f, b = 0.f, c = 0.f;
        for (int k = 0; k < 64; k++) {
            float w = w_ih[t * 64 + k];
            a += w * csh[k];
            b += w * dsh[k];
            c += w * b2[k];
        }
        g_gc[t] = a;
        g_gd[t] = b;
        g_g0[t] = c + b_ih[t] + b_hh[t];
    }

    // B-fragments for mma.sync m16n8k16 (col-major B, k x n):
    // lane holds col = lane/4; reg r covers k rows kt*16 + r*8 + 2*(lane%4)+{0,1}
    // warp w, tile tau: column c (0..7) = kout_local -> w_hh row tau*64 + w*8 + c
    for (int idx = t; idx < 4096; idx += 256) {
        int lane = idx & 31;
        int kt   = (idx >> 5) & 3;
        int tau  = (idx >> 7) & 3;
        int w    = idx >> 9;
        int col  = lane >> 2;
        int nrow = tau * 64 + w * 8 + col;
        int k0   = kt * 16 + 2 * (lane & 3);
        const float* wr = w_hh + nrow * 64;
        float w0 = wr[k0],     w1 = wr[k0 + 1];
        float w8 = wr[k0 + 8], w9 = wr[k0 + 9];
        float h0 = __bfloat162float(__float2bfloat16_rn(w0));
        float h1 = __bfloat162float(__float2bfloat16_rn(w1));
        float h8 = __bfloat162float(__float2bfloat16_rn(w8));
        float h9 = __bfloat162float(__float2bfloat16_rn(w9));
        uint4 q;
        q.x = pack_bf2(w0, w1);
        q.y = pack_bf2(w8, w9);
        q.z = pack_bf2(w0 - h0, w1 - h1);
        q.w = pack_bf2(w8 - h8, w9 - h9);
        g_Bfrag[idx] = q;
    }
}

// ---------------------------------------------------------------------------
// Kernel 2: transpose inputs into F[v][n]  (n = branch*48 + b*12 + t)
// ---------------------------------------------------------------------------
__global__ void k_transpose(const float* __restrict__ ten, const float* __restrict__ per) {
    int i = blockIdx.x * 256 + threadIdx.x;   // < Vn*NN
    int v = i / NN, n = i % NN;
    const float* src = (n < 48) ? ten : per;
    int nl = n % 48;
    g_Ft[i] = src[nl * Vn + v];
}

// ---------------------------------------------------------------------------
// Kernel 3: vertex degree per hypergraph
// ---------------------------------------------------------------------------
__global__ void k_deg(const int* __restrict__ edges) {
    int i = blockIdx.x * 256 + threadIdx.x;   // < NH*ES
    int h = i / ES;
    atomicAdd(&g_degi[h * Vn + edges[i]], 1);
}

__global__ void k_rdeg() {
    int i = blockIdx.x * 256 + threadIdx.x;
    if (i < NH * Vn) {
        int dg = g_degi[i];
        g_rdeg[i] = 1.0f / (float)(dg > 0 ? dg : 1);
    }
}

// ---------------------------------------------------------------------------
// Kernel 4: a1[h][e][n] = mean_s F[edges[h,e,s]][n]   (float4 over n)
// ---------------------------------------------------------------------------
__global__ void k_gather_a1(const int* __restrict__ edges) {
    int i = blockIdx.x * 256 + threadIdx.x;   // < NH*NE*24
    int n4 = (i % 24) * 4;
    int e  = (i / 24) % NE;
    int h  = i / (24 * NE);
    const int* ep = edges + (h * NE + e) * NS;
    float4 acc = make_float4(0.f, 0.f, 0.f, 0.f);
    #pragma unroll
    for (int s = 0; s < NS; s++) {
        const float4 f = *(const float4*)&g_Ft[ep[s] * NN + n4];
        acc.x += f.x; acc.y += f.y; acc.z += f.z; acc.w += f.w;
    }
    const float r = 1.0f / NS;
    acc.x *= r; acc.y *= r; acc.z *= r; acc.w *= r;
    *(float4*)&g_a1[(h * NE + e) * NN + n4] = acc;
}

// ---------------------------------------------------------------------------
// Kernel 5: scatter a1 -> s1 raw sums (vectorized red.global.add.v4.f32)
// ---------------------------------------------------------------------------
__device__ __forceinline__ void red_v4(float* p, float4 v) {
    asm volatile("red.global.add.v4.f32 [%0], {%1, %2, %3, %4};"
                 :: "l"(p), "f"(v.x), "f"(v.y), "f"(v.z), "f"(v.w) : "memory");
}

__global__ void k_scatter_s1(const int* __restrict__ edges) {
    int i = blockIdx.x * 256 + threadIdx.x;   // < NH*ES*24
    int n4   = (i % 24) * 4;
    int slot = (i / 24) % ES;
    int h    = i / (24 * ES);
    int v = edges[h * ES + slot];
    int e = slot >> 5;
    float4 a = *(const float4*)&g_a1[(h * NE + e) * NN + n4];
    red_v4(&g_s1[(h * Vn + v) * NN + n4], a);
}

// ---------------------------------------------------------------------------
// Kernel 6: m1[h][e][n] = mean_s ( s1[edges]/deg )
// ---------------------------------------------------------------------------
__global__ void k_gather_m1(const int* __restrict__ edges) {
    int i = blockIdx.x * 256 + threadIdx.x;   // < NH*NE*24
    int n4 = (i % 24) * 4;
    int e  = (i / 24) % NE;
    int h  = i / (24 * NE);
    const int* ep = edges + (h * NE + e) * NS;
    float4 acc = make_float4(0.f, 0.f, 0.f, 0.f);
    #pragma unroll
    for (int s = 0; s < NS; s++) {
        int v = ep[s];
        float rd = g_rdeg[h * Vn + v];
        const float4 f = *(const float4*)&g_s1[(h * Vn + v) * NN + n4];
        acc.x += f.x * rd; acc.y += f.y * rd; acc.z += f.z * rd; acc.w += f.w * rd;
    }
    const float r = 1.0f / NS;
    acc.x *= r; acc.y *= r; acc.z *= r; acc.w *= r;
    *(float4*)&g_m1[(h * NE + e) * NN + n4] = acc;
}

// ---------------------------------------------------------------------------
// Kernel 7: scatter m1 -> traw
// ---------------------------------------------------------------------------
__global__ void k_scatter_t(const int* __restrict__ edges) {
    int i = blockIdx.x * 256 + threadIdx.x;   // < NH*ES*24
    int n4   = (i % 24) * 4;
    int slot = (i / 24) % ES;
    int h    = i / (24 * ES);
    int v = edges[h * ES + slot];
    int e = slot >> 5;
    float4 a = *(const float4*)&g_m1[(h * NE + e) * NN + n4];
    red_v4(&g_traw[(h * Vn + v) * NN + n4], a);
}

// ---------------------------------------------------------------------------
// Kernel 8: attention over H=3 (scalar form) -> T, P fields
// ---------------------------------------------------------------------------
__global__ void k_attn() {
    int i = blockIdx.x * 256 + threadIdx.x;   // < NN*Vn, layout [n][v]
    int v = i % Vn;
    int n = i / Vn;

    float CT = g_sc[0], DT = g_sc[1], BT = g_sc[2];
    float CB = g_sc[3], DB = g_sc[4], BB = g_sc[5];

    float tv[NH], uf[NH];
    #pragma unroll
    for (int h = 0; h < NH; h++) {
        int idx = h * Vn + v;
        int dg = g_degi[idx];
        uf[h] = (dg > 0) ? 1.0f : 0.0f;
        tv[h] = g_traw[idx * NN + n] * g_rdeg[idx];
    }
    float tbar = (tv[0] + tv[1] + tv[2]) * (1.0f / 3.0f);
    float usum = uf[0] + uf[1] + uf[2];
    float zc = CB * tbar + BB + usum * (1.0f / 3.0f) * DB;

    float z[NH];
    #pragma unroll
    for (int h = 0; h < NH; h++) {
        float zz = CT * tv[h] + uf[h] * DT + BT + zc;
        z[h] = (zz > 0.f) ? zz : 0.2f * zz;     // leaky_relu(0.2)
    }
    float m = fmaxf(z[0], fmaxf(z[1], z[2]));
    float e0 = __expf(z[0] - m), e1 = __expf(z[1] - m), e2 = __expf(z[2] - m);
    float rden = 1.0f / (e0 + e1 + e2);
    g_T[i] = (e0 * tv[0] + e1 * tv[1] + e2 * tv[2]) * rden;
    g_P[i] = (e0 * uf[0] + e1 * uf[1] + e2 * uf[2]) * rden;
}

// ---------------------------------------------------------------------------
// Kernel 9: warp-MMA LSTM. 64 sequences / CTA, 8 warps, grid 1250.
//
//  per step: gates(64x256 fp32 in D-frags) = h(64x64)@W_hh^T, via
//  mma.sync m16n8k16 bf16 3-pass hi/lo split, fp32 accumulate.
//  Warp w owns 32 gate-columns arranged as 4 n-tiles (tau = gate index),
//  in-tile column = kout_local, so each lane gets all 4 gates of
//  kouts w*8+2*(lane%4)+{0,1} for seq rows lane/4 (+8) of each m-tile.
//  h double-buffered in shared as bf16 hi/lo, 144B row stride (odd*16B
//  -> conflict-free ldmatrix). W fragments resident in registers.
// ---------------------------------------------------------------------------
#define HROW 144                      // bytes per h row (72 bf16)
#define HBUF_PART 9216                // 64 rows * 144
#define HBUF_BUF  18432               // hi + lo

__global__ void __launch_bounds__(256) k_lstm_mma(const float* __restrict__ w_out,
                                                  float* __restrict__ out) {
    __shared__ __align__(16) char hbuf[2 * HBUF_BUF];   // 36864 B
    __shared__ float Tsh[NTT * 64], Psh[NTT * 64];
    __shared__ float psum[64];

    const int tid  = threadIdx.x;
    const int wid  = tid >> 5;
    const int lane = tid & 31;
    const int sb   = blockIdx.x * 64;
    const int bo   = (sb >= 40000) ? 64 : 0;      // w_out branch offset
    const int m2   = lane & 3;
    const int kg0  = wid * 8 + 2 * m2;            // this lane's kout pair

    // ---- resident B fragments (64 regs) ----
    uint32_t Bh[4][4][2], Bl[4][4][2];
    #pragma unroll
    for (int tau = 0; tau < 4; tau++)
        #pragma unroll
        for (int kt = 0; kt < 4; kt++) {
            uint4 q = g_Bfrag[((wid * 4 + tau) * 4 + kt) * 32 + lane];
            Bh[tau][kt][0] = q.x; Bh[tau][kt][1] = q.y;
            Bl[tau][kt][0] = q.z; Bl[tau][kt][1] = q.w;
        }

    // ---- projection coefficients for this lane's 2 kouts x 4 gates ----
    float gcv[4][2], gdv[4][2], g0v[4][2];
    #pragma unroll
    for (int tau = 0; tau < 4; tau++) {
        gcv[tau][0] = g_gc[tau * 64 + kg0];     gcv[tau][1] = g_gc[tau * 64 + kg0 + 1];
        gdv[tau][0] = g_gd[tau * 64 + kg0];     gdv[tau][1] = g_gd[tau * 64 + kg0 + 1];
        g0v[tau][0] = g_g0[tau * 64 + kg0];     g0v[tau][1] = g_g0[tau * 64 + kg0 + 1];
    }
    const float wo0 = w_out[bo + kg0], wo1 = w_out[bo + kg0 + 1];

    // ---- T/P for this CTA's 64 seqs x 12 steps ----
    for (int idx = tid; idx < NTT * 64; idx += 256) {
        int s = idx & 63, tt = idx >> 6;
        int sq = sb + s;
        int branch = sq / 40000;
        int rem = sq - branch * 40000;
        int b = rem / Vn;
        int v = rem - b * Vn;
        int n = branch * 48 + b * 12 + tt;
        Tsh[tt * 64 + s] = g_T[n * Vn + v];
        Psh[tt * 64 + s] = g_P[n * Vn + v];
    }
    if (tid < 64) psum[tid] = 0.f;
    __syncthreads();

    const uint32_t hb32 = smem_u32(hbuf);
    // ldmatrix per-lane row address components
    const int grp   = lane >> 3;
    const int arow_local = ((grp & 1) << 3) + (lane & 7);   // row within 16-row tile
    const uint32_t acolb = (uint32_t)(grp >> 1) * 16;       // byte col (k half)

    float cst[4][2][2];                 // [mtile][rowhalf][e]
    #pragma unroll
    for (int a = 0; a < 4; a++)
        #pragma unroll
        for (int b = 0; b < 2; b++) { cst[a][b][0] = 0.f; cst[a][b][1] = 0.f; }

    for (int t = 0; t < NTT; t++) {
        const int rb = t & 1, wb = rb ^ 1;
        #pragma unroll
        for (int mt = 0; mt < 4; mt++) {
            const int r0 = mt * 16 + (lane >> 2);
            const float T0 = Tsh[t * 64 + r0],     P0 = Psh[t * 64 + r0];
            const float T1 = Tsh[t * 64 + r0 + 8], P1 = Psh[t * 64 + r0 + 8];

            float D[4][4];
            #pragma unroll
            for (int tau = 0; tau < 4; tau++) {
                D[tau][0] = fmaf(T0, gcv[tau][0], fmaf(P0, gdv[tau][0], g0v[tau][0]));
                D[tau][1] = fmaf(T0, gcv[tau][1], fmaf(P0, gdv[tau][1], g0v[tau][1]));
                D[tau][2] = fmaf(T1, gcv[tau][0], fmaf(P1, gdv[tau][0], g0v[tau][0]));
                D[tau][3] = fmaf(T1, gcv[tau][1], fmaf(P1, gdv[tau][1], g0v[tau][1]));
            }

            if (t > 0) {
                uint32_t Ah[4][4], Al[4][4];
                const uint32_t abase = hb32 + (uint32_t)rb * HBUF_BUF
                                     + (uint32_t)(mt * 16 + arow_local) * HROW + acolb;
                #pragma unroll
                for (int kt = 0; kt < 4; kt++) {
                    ldsm4(Ah[kt], abase + (uint32_t)kt * 32);
                    ldsm4(Al[kt], abase + HBUF_PART + (uint32_t)kt * 32);
                }
                #pragma unroll
                for (int tau = 0; tau < 4; tau++)
                    #pragma unroll
                    for (int kt = 0; kt < 4; kt++) {
                        mma_bf16(D[tau], Ah[kt], Bh[tau][kt]);
                        mma_bf16(D[tau], Al[kt], Bh[tau][kt]);
                        mma_bf16(D[tau], Ah[kt], Bl[tau][kt]);
                    }
            }

            // epilogue: 2 rows x 2 kouts per lane
            #pragma unroll
            for (int rh = 0; rh < 2; rh++) {
                float hv[2];
                #pragma unroll
                for (int e = 0; e < 2; e++) {
                    const int c = rh * 2 + e;
                    float gi = D[0][c], gf = D[1][c], gg = D[2][c], go = D[3][c];
                    float cn = sigm(gf) * cst[mt][rh][e] + sigm(gi) * tanh_e(gg);
                    cst[mt][rh][e] = cn;
                    hv[e] = sigm(go) * tanh_e(cn);
                }
                const int row = r0 + rh * 8;
                if (t == NTT - 1) {
                    atomicAdd(&psum[row], hv[0] * wo0 + hv[1] * wo1);
                } else {
                    __nv_bfloat16 b0 = __float2bfloat16_rn(hv[0]);
                    __nv_bfloat16 b1 = __float2bfloat16_rn(hv[1]);
                    __nv_bfloat162 ph = make_bfloat162(b0, b1);
                    __nv_bfloat162 pl = make_bfloat162(
                        __float2bfloat16_rn(hv[0] - __bfloat162float(b0)),
                        __float2bfloat16_rn(hv[1] - __bfloat162float(b1)));
                    char* dst = hbuf + wb * HBUF_BUF + row * HROW + kg0 * 2;
                    *(uint32_t*)dst               = *(uint32_t*)&ph;
                    *(uint32_t*)(dst + HBUF_PART) = *(uint32_t*)&pl;
                }
            }
        }
        __syncthreads();
    }

    if (tid < 64) {
        int rem = (sb + tid) % 40000;             // = b*V + v
        atomicAdd(&out[rem], psum[tid]);
    }
}

// ---------------------------------------------------------------------------
// Host launch
// ---------------------------------------------------------------------------
extern "C" void kernel_launch(void* const* d_in, const int* in_sizes, int n_in,
                              void* d_out, int out_size) {
    const float* tendency    = (const float*)d_in[0];
    const float* periodicity = (const float*)d_in[1];
    const int*   edges       = (const int*)  d_in[2];
    const float* w1          = (const float*)d_in[3];
    const float* b1          = (const float*)d_in[4];
    const float* w2          = (const float*)d_in[5];
    const float* b2          = (const float*)d_in[6];
    const float* attn_w      = (const float*)d_in[7];
    const float* attn_a      = (const float*)d_in[8];
    const float* w_ih        = (const float*)d_in[9];
    const float* w_hh        = (const float*)d_in[10];
    const float* b_ih        = (const float*)d_in[11];
    const float* b_hh        = (const float*)d_in[12];
    const float* w_out       = (const float*)d_in[13];
    const float* b_out       = (const float*)d_in[14];
    float* out = (float*)d_out;

    k_zero      <<<11250, 256>>>(out, b_out);
    k_prep      <<<1,     256>>>(w1, b1, w2, b2, attn_w, attn_a, w_ih, w_hh, b_ih, b_hh);
    k_transpose <<<3750,  256>>>(tendency, periodicity);
    k_deg       <<<(NH * ES) / 256, 256>>>(edges);            // 192 blocks
    k_rdeg      <<<(NH * Vn + 255) / 256, 256>>>();
    k_gather_a1 <<<(NH * NE * 24) / 256, 256>>>(edges);       // 144
    k_scatter_s1<<<(NH * ES * 24) / 256, 256>>>(edges);       // 4608
    k_gather_m1 <<<(NH * NE * 24) / 256, 256>>>(edges);
    k_scatter_t <<<(NH * ES * 24) / 256, 256>>>(edges);
    k_attn      <<<3750,  256>>>();
    k_lstm_mma  <<<1250,  256>>>(w_out, out);
}

// round 13
// speedup vs baseline: 4.4452x; 1.0006x over previous
#include <cuda_runtime.h>
#include <cuda_bf16.h>
#include <stdint.h>

// ---------------------------------------------------------------------------
// Problem constants
// ---------------------------------------------------------------------------
#define Vn   10000
#define NBAT 4
#define NTT  12
#define NN   96          // 2 branches * 4 * 12
#define NH   3
#define NE   512
#define NS   32
#define ES   (NE*NS)     // 16384

typedef unsigned long long u64;

// ---------------------------------------------------------------------------
// Device scratch (static allocation; no cudaMalloc allowed)
// ---------------------------------------------------------------------------
__device__ float g_Ft   [Vn * NN];        // transposed inputs F[v][n]
__device__ int   g_degi [NH * Vn];        // vertex degree per hypergraph
__device__ float g_rdeg [NH * Vn];        // 1 / max(deg,1)
__device__ float g_a1   [NH * NE * NN];   // layer-1 edge means
__device__ float g_s1   [NH * Vn * NN];   // layer-1 raw scatter sums
__device__ float g_m1   [NH * NE * NN];   // layer-2 edge means
__device__ float g_traw [NH * Vn * NN];   // layer-2 raw scatter sums
__device__ float g_T    [NN * Vn];        // attention-fused scalar field (t)
__device__ float g_P    [NN * Vn];        // attention-fused incidence field
__device__ float g_gc   [256];            // w_ih @ c   [gate*64+kout]
__device__ float g_gd   [256];            // w_ih @ d
__device__ float g_g0   [256];            // w_ih @ b2 + b_ih + b_hh
__device__ float g_sc   [6];              // CT, DT, BT, CB, DB, BB
// W_hh mma B-fragments, per-lane register layout:
// index ((w*4 + tau)*4 + kt)*32 + lane -> {bhi0, bhi1, blo0, blo1}
__device__ uint4 g_Bfrag[8 * 4 * 4 * 32];

// ---------------------------------------------------------------------------
// Math helpers (fp32, exp-based — proven 1e-7 accurate in R3)
// ---------------------------------------------------------------------------
__device__ __forceinline__ float sigm(float x) {
    float t = __expf(-x);
    return __fdividef(1.0f, 1.0f + t);
}
__device__ __forceinline__ float tanh_e(float x) {
    x = fminf(fmaxf(x, -8.0f), 8.0f);
    float t = __expf(2.0f * x);
    return __fdividef(t - 1.0f, t + 1.0f);
}

__device__ __forceinline__ uint32_t smem_u32(const void* p) {
    uint32_t a;
    asm("{ .reg .u64 t; cvta.to.shared.u64 t, %1; cvt.u32.u64 %0, t; }"
        : "=r"(a) : "l"(p));
    return a;
}

// classic warp-level bf16 MMA, fp32 accumulate (sm_80+, works on plain sm_103)
__device__ __forceinline__ void mma_bf16(float* d, const uint32_t* a, const uint32_t* b) {
    asm volatile("mma.sync.aligned.m16n8k16.row.col.f32.bf16.bf16.f32 "
        "{%0,%1,%2,%3}, {%4,%5,%6,%7}, {%8,%9}, {%0,%1,%2,%3};"
        : "+f"(d[0]), "+f"(d[1]), "+f"(d[2]), "+f"(d[3])
        : "r"(a[0]), "r"(a[1]), "r"(a[2]), "r"(a[3]), "r"(b[0]), "r"(b[1]));
}
__device__ __forceinline__ void ldsm4(uint32_t* r, uint32_t addr) {
    asm volatile("ldmatrix.sync.aligned.m8n8.x4.shared.b16 {%0,%1,%2,%3}, [%4];"
        : "=r"(r[0]), "=r"(r[1]), "=r"(r[2]), "=r"(r[3]) : "r"(addr));
}

// ---------------------------------------------------------------------------
// Kernel 0: zero scratch + init output to b_out
// ---------------------------------------------------------------------------
__global__ void k_zero(float* __restrict__ out, const float* __restrict__ b_out) {
    int i = blockIdx.x * 256 + threadIdx.x;   // grid covers NH*Vn*NN = 2,880,000
    g_s1[i]   = 0.f;
    g_traw[i] = 0.f;
    if (i < NH * Vn) g_degi[i] = 0;
    if (i < NBAT * Vn) out[i] = b_out[0];
}

// ---------------------------------------------------------------------------
// Kernel 1: precompute weight-derived constants (1 block, 256 threads)
// ---------------------------------------------------------------------------
__device__ __forceinline__ uint32_t pack_bf2(float a, float b) {
    __nv_bfloat162 p = make_bfloat162(__float2bfloat16_rn(a), __float2bfloat16_rn(b));
    return *(uint32_t*)&p;
}

__global__ void k_prep(const float* __restrict__ w1,     const float* __restrict__ b1,
                       const float* __restrict__ w2,     const float* __restrict__ b2,
                       const float* __restrict__ attn_w, const float* __restrict__ attn_a,
                       const float* __restrict__ w_ih,   const float* __restrict__ w_hh,
                       const float* __restrict__ b_ih,   const float* __restrict__ b_hh) {
    __shared__ float csh[64], dsh[64], cw[64], dw[64], bw[64];
    int t = threadIdx.x;

    if (t < 64) {
        float c = 0.f, d = 0.f;
        for (int i = 0; i < 64; i++) {
            float w = w2[i * 64 + t];
            c += w1[i] * w;
            d += b1[i] * w;
        }
        csh[t] = c; dsh[t] = d;
    }
    __syncthreads();

    if (t < 64) {
        float a = 0.f, b = 0.f, c = 0.f;
        for (int i = 0; i < 64; i++) {
            float w = attn_w[i * 64 + t];
            a += csh[i] * w;
            b += dsh[i] * w;
            c += b2[i]  * w;
        }
        cw[t] = a; dw[t] = b; bw[t] = c;
    }
    __syncthreads();

    if (t == 0) {
        float CT=0,DT=0,BT=0,CB=0,DB=0,BB=0;
        for (int j = 0; j < 64; j++) {
            float at = attn_a[j], ab = attn_a[64 + j];
            CT += cw[j]*at; DT += dw[j]*at; BT += bw[j]*at;
            CB += cw[j]*ab; DB += dw[j]*ab; BB += bw[j]*ab;
        }
        g_sc[0]=CT; g_sc[1]=DT; g_sc[2]=BT; g_sc[3]=CB; g_sc[4]=DB; g_sc[5]=BB;
    }

    // gc/gd/g0 for LSTM input projection, layout [gate*64+kout]
    {
        float a = 0.f, b = 0.f, c = 0.f;
        for (int k = 0; k < 64; k++) {
            float w = w_ih[t * 64 + k];
            a += w * csh[k];
            b += w * dsh[k];
            c += w * b2[k];
        }
        g_gc[t] = a;
        g_gd[t] = b;
        g_g0[t] = c + b_ih[t] + b_hh[t];
    }

    // B-fragments for mma.sync m16n8k16 (col-major B, k x n):
    // lane holds col = lane/4; reg r covers k rows kt*16 + r*8 + 2*(lane%4)+{0,1}
    // warp w, tile tau: column c (0..7) = kout_local -> w_hh row tau*64 + w*8 + c
    for (int idx = t; idx < 4096; idx += 256) {
        int lane = idx & 31;
        int kt   = (idx >> 5) & 3;
        int tau  = (idx >> 7) & 3;
        int w    = idx >> 9;
        int col  = lane >> 2;
        int nrow = tau * 64 + w * 8 + col;
        int k0   = kt * 16 + 2 * (lane & 3);
        const float* wr = w_hh + nrow * 64;
        float w0 = wr[k0],     w1 = wr[k0 + 1];
        float w8 = wr[k0 + 8], w9 = wr[k0 + 9];
        float h0 = __bfloat162float(__float2bfloat16_rn(w0));
        float h1 = __bfloat162float(__float2bfloat16_rn(w1));
        float h8 = __bfloat162float(__float2bfloat16_rn(w8));
        float h9 = __bfloat162float(__float2bfloat16_rn(w9));
        uint4 q;
        q.x = pack_bf2(w0, w1);
        q.y = pack_bf2(w8, w9);
        q.z = pack_bf2(w0 - h0, w1 - h1);
        q.w = pack_bf2(w8 - h8, w9 - h9);
        g_Bfrag[idx] = q;
    }
}

// ---------------------------------------------------------------------------
// Kernel 2: transpose inputs into F[v][n]  (n = branch*48 + b*12 + t)
// ---------------------------------------------------------------------------
__global__ void k_transpose(const float* __restrict__ ten, const float* __restrict__ per) {
    int i = blockIdx.x * 256 + threadIdx.x;   // < Vn*NN
    int v = i / NN, n = i % NN;
    const float* src = (n < 48) ? ten : per;
    int nl = n % 48;
    g_Ft[i] = src[nl * Vn + v];
}

// ---------------------------------------------------------------------------
// Kernel 3: vertex degree per hypergraph
// ---------------------------------------------------------------------------
__global__ void k_deg(const int* __restrict__ edges) {
    int i = blockIdx.x * 256 + threadIdx.x;   // < NH*ES
    int h = i / ES;
    atomicAdd(&g_degi[h * Vn + edges[i]], 1);
}

__global__ void k_rdeg() {
    int i = blockIdx.x * 256 + threadIdx.x;
    if (i < NH * Vn) {
        int dg = g_degi[i];
        g_rdeg[i] = 1.0f / (float)(dg > 0 ? dg : 1);
    }
}

// ---------------------------------------------------------------------------
// Kernel 4: a1[h][e][n] = mean_s F[edges[h,e,s]][n]   (float4 over n)
// ---------------------------------------------------------------------------
__global__ void k_gather_a1(const int* __restrict__ edges) {
    int i = blockIdx.x * 256 + threadIdx.x;   // < NH*NE*24
    int n4 = (i % 24) * 4;
    int e  = (i / 24) % NE;
    int h  = i / (24 * NE);
    const int* ep = edges + (h * NE + e) * NS;
    float4 acc = make_float4(0.f, 0.f, 0.f, 0.f);
    #pragma unroll
    for (int s = 0; s < NS; s++) {
        const float4 f = *(const float4*)&g_Ft[ep[s] * NN + n4];
        acc.x += f.x; acc.y += f.y; acc.z += f.z; acc.w += f.w;
    }
    const float r = 1.0f / NS;
    acc.x *= r; acc.y *= r; acc.z *= r; acc.w *= r;
    *(float4*)&g_a1[(h * NE + e) * NN + n4] = acc;
}

// ---------------------------------------------------------------------------
// Kernel 5: scatter a1 -> s1 raw sums (vectorized red.global.add.v4.f32)
// ---------------------------------------------------------------------------
__device__ __forceinline__ void red_v4(float* p, float4 v) {
    asm volatile("red.global.add.v4.f32 [%0], {%1, %2, %3, %4};"
                 :: "l"(p), "f"(v.x), "f"(v.y), "f"(v.z), "f"(v.w) : "memory");
}

__global__ void k_scatter_s1(const int* __restrict__ edges) {
    int i = blockIdx.x * 256 + threadIdx.x;   // < NH*ES*24
    int n4   = (i % 24) * 4;
    int slot = (i / 24) % ES;
    int h    = i / (24 * ES);
    int v = edges[h * ES + slot];
    int e = slot >> 5;
    float4 a = *(const float4*)&g_a1[(h * NE + e) * NN + n4];
    red_v4(&g_s1[(h * Vn + v) * NN + n4], a);
}

// ---------------------------------------------------------------------------
// Kernel 6: m1[h][e][n] = mean_s ( s1[edges]/deg )
// ---------------------------------------------------------------------------
__global__ void k_gather_m1(const int* __restrict__ edges) {
    int i = blockIdx.x * 256 + threadIdx.x;   // < NH*NE*24
    int n4 = (i % 24) * 4;
    int e  = (i / 24) % NE;
    int h  = i / (24 * NE);
    const int* ep = edges + (h * NE + e) * NS;
    float4 acc = make_float4(0.f, 0.f, 0.f, 0.f);
    #pragma unroll
    for (int s = 0; s < NS; s++) {
        int v = ep[s];
        float rd = g_rdeg[h * Vn + v];
        const float4 f = *(const float4*)&g_s1[(h * Vn + v) * NN + n4];
        acc.x += f.x * rd; acc.y += f.y * rd; acc.z += f.z * rd; acc.w += f.w * rd;
    }
    const float r = 1.0f / NS;
    acc.x *= r; acc.y *= r; acc.z *= r; acc.w *= r;
    *(float4*)&g_m1[(h * NE + e) * NN + n4] = acc;
}

// ---------------------------------------------------------------------------
// Kernel 7: scatter m1 -> traw
// ---------------------------------------------------------------------------
__global__ void k_scatter_t(const int* __restrict__ edges) {
    int i = blockIdx.x * 256 + threadIdx.x;   // < NH*ES*24
    int n4   = (i % 24) * 4;
    int slot = (i / 24) % ES;
    int h    = i / (24 * ES);
    int v = edges[h * ES + slot];
    int e = slot >> 5;
    float4 a = *(const float4*)&g_m1[(h * NE + e) * NN + n4];
    red_v4(&g_traw[(h * Vn + v) * NN + n4], a);
}

// ---------------------------------------------------------------------------
// Kernel 8: attention over H=3 (scalar form) -> T, P fields
// ---------------------------------------------------------------------------
__global__ void k_attn() {
    int i = blockIdx.x * 256 + threadIdx.x;   // < NN*Vn, layout [n][v]
    int v = i % Vn;
    int n = i / Vn;

    float CT = g_sc[0], DT = g_sc[1], BT = g_sc[2];
    float CB = g_sc[3], DB = g_sc[4], BB = g_sc[5];

    float tv[NH], uf[NH];
    #pragma unroll
    for (int h = 0; h < NH; h++) {
        int idx = h * Vn + v;
        int dg = g_degi[idx];
        uf[h] = (dg > 0) ? 1.0f : 0.0f;
        tv[h] = g_traw[idx * NN + n] * g_rdeg[idx];
    }
    float tbar = (tv[0] + tv[1] + tv[2]) * (1.0f / 3.0f);
    float usum = uf[0] + uf[1] + uf[2];
    float zc = CB * tbar + BB + usum * (1.0f / 3.0f) * DB;

    float z[NH];
    #pragma unroll
    for (int h = 0; h < NH; h++) {
        float zz = CT * tv[h] + uf[h] * DT + BT + zc;
        z[h] = (zz > 0.f) ? zz : 0.2f * zz;     // leaky_relu(0.2)
    }
    float m = fmaxf(z[0], fmaxf(z[1], z[2]));
    float e0 = __expf(z[0] - m), e1 = __expf(z[1] - m), e2 = __expf(z[2] - m);
    float rden = 1.0f / (e0 + e1 + e2);
    g_T[i] = (e0 * tv[0] + e1 * tv[1] + e2 * tv[2]) * rden;
    g_P[i] = (e0 * uf[0] + e1 * uf[1] + e2 * uf[2]) * rden;
}

// ---------------------------------------------------------------------------
// Kernel 9: warp-MMA LSTM. 64 sequences / CTA, 8 warps, grid 1250.
//
//  per step: gates(64x256 fp32 in D-frags) = h(64x64)@W_hh^T, via
//  mma.sync m16n8k16 bf16 3-pass hi/lo split, fp32 accumulate.
//  Warp w owns 32 gate-columns arranged as 4 n-tiles (tau = gate index),
//  in-tile column = kout_local, so each lane gets all 4 gates of
//  kouts w*8+2*(lane%4)+{0,1} for seq rows lane/4 (+8) of each m-tile.
//  h double-buffered in shared as bf16 hi/lo, 144B row stride (odd*16B
//  -> conflict-free ldmatrix). W fragments resident in registers.
// ---------------------------------------------------------------------------
#define HROW 144                      // bytes per h row (72 bf16)
#define HBUF_PART 9216                // 64 rows * 144
#define HBUF_BUF  18432               // hi + lo

__global__ void __launch_bounds__(256) k_lstm_mma(const float* __restrict__ w_out,
                                                  float* __restrict__ out) {
    __shared__ __align__(16) char hbuf[2 * HBUF_BUF];   // 36864 B
    __shared__ float Tsh[NTT * 64], Psh[NTT * 64];
    __shared__ float psum[64];

    const int tid  = threadIdx.x;
    const int wid  = tid >> 5;
    const int lane = tid & 31;
    const int sb   = blockIdx.x * 64;
    const int bo   = (sb >= 40000) ? 64 : 0;      // w_out branch offset
    const int m2   = lane & 3;
    const int kg0  = wid * 8 + 2 * m2;            // this lane's kout pair

    // ---- resident B fragments (64 regs) ----
    uint32_t Bh[4][4][2], Bl[4][4][2];
    #pragma unroll
    for (int tau = 0; tau < 4; tau++)
        #pragma unroll
        for (int kt = 0; kt < 4; kt++) {
            uint4 q = g_Bfrag[((wid * 4 + tau) * 4 + kt) * 32 + lane];
            Bh[tau][kt][0] = q.x; Bh[tau][kt][1] = q.y;
            Bl[tau][kt][0] = q.z; Bl[tau][kt][1] = q.w;
        }

    // ---- projection coefficients for this lane's 2 kouts x 4 gates ----
    float gcv[4][2], gdv[4][2], g0v[4][2];
    #pragma unroll
    for (int tau = 0; tau < 4; tau++) {
        gcv[tau][0] = g_gc[tau * 64 + kg0];     gcv[tau][1] = g_gc[tau * 64 + kg0 + 1];
        gdv[tau][0] = g_gd[tau * 64 + kg0];     gdv[tau][1] = g_gd[tau * 64 + kg0 + 1];
        g0v[tau][0] = g_g0[tau * 64 + kg0];     g0v[tau][1] = g_g0[tau * 64 + kg0 + 1];
    }
    const float wo0 = w_out[bo + kg0], wo1 = w_out[bo + kg0 + 1];

    // ---- T/P for this CTA's 64 seqs x 12 steps ----
    for (int idx = tid; idx < NTT * 64; idx += 256) {
        int s = idx & 63, tt = idx >> 6;
        int sq = sb + s;
        int branch = sq / 40000;
        int rem = sq - branch * 40000;
        int b = rem / Vn;
        int v = rem - b * Vn;
        int n = branch * 48 + b * 12 + tt;
        Tsh[tt * 64 + s] = g_T[n * Vn + v];
        Psh[tt * 64 + s] = g_P[n * Vn + v];
    }
    if (tid < 64) psum[tid] = 0.f;
    __syncthreads();

    const uint32_t hb32 = smem_u32(hbuf);
    // ldmatrix per-lane row address components
    const int grp   = lane >> 3;
    const int arow_local = ((grp & 1) << 3) + (lane & 7);   // row within 16-row tile
    const uint32_t acolb = (uint32_t)(grp >> 1) * 16;       // byte col (k half)

    float cst[4][2][2];                 // [mtile][rowhalf][e]
    #pragma unroll
    for (int a = 0; a < 4; a++)
        #pragma unroll
        for (int b = 0; b < 2; b++) { cst[a][b][0] = 0.f; cst[a][b][1] = 0.f; }

    for (int t = 0; t < NTT; t++) {
        const int rb = t & 1, wb = rb ^ 1;
        #pragma unroll
        for (int mt = 0; mt < 4; mt++) {
            const int r0 = mt * 16 + (lane >> 2);
            const float T0 = Tsh[t * 64 + r0],     P0 = Psh[t * 64 + r0];
            const float T1 = Tsh[t * 64 + r0 + 8], P1 = Psh[t * 64 + r0 + 8];

            float D[4][4];
            #pragma unroll
            for (int tau = 0; tau < 4; tau++) {
                D[tau][0] = fmaf(T0, gcv[tau][0], fmaf(P0, gdv[tau][0], g0v[tau][0]));
                D[tau][1] = fmaf(T0, gcv[tau][1], fmaf(P0, gdv[tau][1], g0v[tau][1]));
                D[tau][2] = fmaf(T1, gcv[tau][0], fmaf(P1, gdv[tau][0], g0v[tau][0]));
                D[tau][3] = fmaf(T1, gcv[tau][1], fmaf(P1, gdv[tau][1], g0v[tau][1]));
            }

            if (t > 0) {
                uint32_t Ah[4][4], Al[4][4];
                const uint32_t abase = hb32 + (uint32_t)rb * HBUF_BUF
                                     + (uint32_t)(mt * 16 + arow_local) * HROW + acolb;
                #pragma unroll
                for (int kt = 0; kt < 4; kt++) {
                    ldsm4(Ah[kt], abase + (uint32_t)kt * 32);
                    ldsm4(Al[kt], abase + HBUF_PART + (uint32_t)kt * 32);
                }
                #pragma unroll
                for (int tau = 0; tau < 4; tau++)
                    #pragma unroll
                    for (int kt = 0; kt < 4; kt++) {
                        mma_bf16(D[tau], Ah[kt], Bh[tau][kt]);
                        mma_bf16(D[tau], Al[kt], Bh[tau][kt]);
                        mma_bf16(D[tau], Ah[kt], Bl[tau][kt]);
                    }
            }

            // epilogue: 2 rows x 2 kouts per lane
            #pragma unroll
            for (int rh = 0; rh < 2; rh++) {
                float hv[2];
                #pragma unroll
                for (int e = 0; e < 2; e++) {
                    const int c = rh * 2 + e;
                    float gi = D[0][c], gf = D[1][c], gg = D[2][c], go = D[3][c];
                    float cn = sigm(gf) * cst[mt][rh][e] + sigm(gi) * tanh_e(gg);
                    cst[mt][rh][e] = cn;
                    hv[e] = sigm(go) * tanh_e(cn);
                }
                const int row = r0 + rh * 8;
                if (t == NTT - 1) {
                    atomicAdd(&psum[row], hv[0] * wo0 + hv[1] * wo1);
                } else {
                    __nv_bfloat16 b0 = __float2bfloat16_rn(hv[0]);
                    __nv_bfloat16 b1 = __float2bfloat16_rn(hv[1]);
                    __nv_bfloat162 ph = make_bfloat162(b0, b1);
                    __nv_bfloat162 pl = make_bfloat162(
                        __float2bfloat16_rn(hv[0] - __bfloat162float(b0)),
                        __float2bfloat16_rn(hv[1] - __bfloat162float(b1)));
                    char* dst = hbuf + wb * HBUF_BUF + row * HROW + kg0 * 2;
                    *(uint32_t*)dst               = *(uint32_t*)&ph;
                    *(uint32_t*)(dst + HBUF_PART) = *(uint32_t*)&pl;
                }
            }
        }
        __syncthreads();
    }

    if (tid < 64) {
        int rem = (sb + tid) % 40000;             // = b*V + v
        atomicAdd(&out[rem], psum[tid]);
    }
}

// ---------------------------------------------------------------------------
// Host launch
// ---------------------------------------------------------------------------
extern "C" void kernel_launch(void* const* d_in, const int* in_sizes, int n_in,
                              void* d_out, int out_size) {
    const float* tendency    = (const float*)d_in[0];
    const float* periodicity = (const float*)d_in[1];
    const int*   edges       = (const int*)  d_in[2];
    const float* w1          = (const float*)d_in[3];
    const float* b1          = (const float*)d_in[4];
    const float* w2          = (const float*)d_in[5];
    const float* b2          = (const float*)d_in[6];
    const float* attn_w      = (const float*)d_in[7];
    const float* attn_a      = (const float*)d_in[8];
    const float* w_ih        = (const float*)d_in[9];
    const float* w_hh        = (const float*)d_in[10];
    const float* b_ih        = (const float*)d_in[11];
    const float* b_hh        = (const float*)d_in[12];
    const float* w_out       = (const float*)d_in[13];
    const float* b_out       = (const float*)d_in[14];
    float* out = (float*)d_out;

    k_zero      <<<11250, 256>>>(out, b_out);
    k_prep      <<<1,     256>>>(w1, b1, w2, b2, attn_w, attn_a, w_ih, w_hh, b_ih, b_hh);
    k_transpose <<<3750,  256>>>(tendency, periodicity);
    k_deg       <<<(NH * ES) / 256, 256>>>(edges);            // 192 blocks
    k_rdeg      <<<(NH * Vn + 255) / 256, 256>>>();
    k_gather_a1 <<<(NH * NE * 24) / 256, 256>>>(edges);       // 144
    k_scatter_s1<<<(NH * ES * 24) / 256, 256>>>(edges);       // 4608
    k_gather_m1 <<<(NH * NE * 24) / 256, 256>>>(edges);
    k_scatter_t <<<(NH * ES * 24) / 256, 256>>>(edges);
    k_attn      <<<3750,  256>>>();
    k_lstm_mma  <<<1250,  256>>>(w_out, out);
}

// round 14
// speedup vs baseline: 4.4492x; 1.0009x over previous
#include <cuda_runtime.h>
#include <cuda_bf16.h>
#include <stdint.h>

// ---------------------------------------------------------------------------
// Problem constants
// ---------------------------------------------------------------------------
#define Vn   10000
#define NBAT 4
#define NTT  12
#define NN   96          // 2 branches * 4 * 12
#define NH   3
#define NE   512
#define NS   32
#define ES   (NE*NS)     // 16384

typedef unsigned long long u64;

// ---------------------------------------------------------------------------
// Device scratch (static allocation; no cudaMalloc allowed)
// ---------------------------------------------------------------------------
__device__ float g_Ft   [Vn * NN];        // transposed inputs F[v][n]
__device__ int   g_degi [NH * Vn];        // vertex degree per hypergraph
__device__ float g_rdeg [NH * Vn];        // 1 / max(deg,1)
__device__ float g_a1   [NH * NE * NN];   // layer-1 edge means
__device__ float g_s1   [NH * Vn * NN];   // layer-1 raw scatter sums
__device__ float g_m1   [NH * NE * NN];   // layer-2 edge means
__device__ float g_traw [NH * Vn * NN];   // layer-2 raw scatter sums
__device__ float g_T    [NN * Vn];        // attention-fused scalar field (t)
__device__ float g_P    [NN * Vn];        // attention-fused incidence field
__device__ float g_gc   [256];            // w_ih @ c   [gate*64+kout]
__device__ float g_gd   [256];            // w_ih @ d
__device__ float g_g0   [256];            // w_ih @ b2 + b_ih + b_hh
__device__ float g_sc   [6];              // CT, DT, BT, CB, DB, BB
// W_hh mma B-fragments, per-lane register layout:
// index ((w*4 + tau)*4 + kt)*32 + lane -> {bhi0, bhi1, blo0, blo1}
__device__ uint4 g_Bfrag[8 * 4 * 4 * 32];

// ---------------------------------------------------------------------------
// Math helpers (fp32, exp-based — proven 1e-7 accurate in R3)
// ---------------------------------------------------------------------------
__device__ __forceinline__ float sigm(float x) {
    float t = __expf(-x);
    return __fdividef(1.0f, 1.0f + t);
}
__device__ __forceinline__ float tanh_e(float x) {
    x = fminf(fmaxf(x, -8.0f), 8.0f);
    float t = __expf(2.0f * x);
    return __fdividef(t - 1.0f, t + 1.0f);
}

__device__ __forceinline__ uint32_t smem_u32(const void* p) {
    uint32_t a;
    asm("{ .reg .u64 t; cvta.to.shared.u64 t, %1; cvt.u32.u64 %0, t; }"
        : "=r"(a) : "l"(p));
    return a;
}

// classic warp-level bf16 MMA, fp32 accumulate (sm_80+, works on plain sm_103)
__device__ __forceinline__ void mma_bf16(float* d, const uint32_t* a, const uint32_t* b) {
    asm volatile("mma.sync.aligned.m16n8k16.row.col.f32.bf16.bf16.f32 "
        "{%0,%1,%2,%3}, {%4,%5,%6,%7}, {%8,%9}, {%0,%1,%2,%3};"
        : "+f"(d[0]), "+f"(d[1]), "+f"(d[2]), "+f"(d[3])
        : "r"(a[0]), "r"(a[1]), "r"(a[2]), "r"(a[3]), "r"(b[0]), "r"(b[1]));
}
__device__ __forceinline__ void ldsm4(uint32_t* r, uint32_t addr) {
    asm volatile("ldmatrix.sync.aligned.m8n8.x4.shared.b16 {%0,%1,%2,%3}, [%4];"
        : "=r"(r[0]), "=r"(r[1]), "=r"(r[2]), "=r"(r[3]) : "r"(addr));
}

// ---------------------------------------------------------------------------
// Kernel 0: zero scratch + init output to b_out
// ---------------------------------------------------------------------------
__global__ void k_zero(float* __restrict__ out, const float* __restrict__ b_out) {
    int i = blockIdx.x * 256 + threadIdx.x;   // grid covers NH*Vn*NN = 2,880,000
    g_s1[i]   = 0.f;
    g_traw[i] = 0.f;
    if (i < NH * Vn) g_degi[i] = 0;
    if (i < NBAT * Vn) out[i] = b_out[0];
}

// ---------------------------------------------------------------------------
// Kernel 1: precompute weight-derived constants (1 block, 256 threads)
// ---------------------------------------------------------------------------
__device__ __forceinline__ uint32_t pack_bf2(float a, float b) {
    __nv_bfloat162 p = make_bfloat162(__float2bfloat16_rn(a), __float2bfloat16_rn(b));
    return *(uint32_t*)&p;
}

__global__ void k_prep(const float* __restrict__ w1,     const float* __restrict__ b1,
                       const float* __restrict__ w2,     const float* __restrict__ b2,
                       const float* __restrict__ attn_w, const float* __restrict__ attn_a,
                       const float* __restrict__ w_ih,   const float* __restrict__ w_hh,
                       const float* __restrict__ b_ih,   const float* __restrict__ b_hh) {
    __shared__ float csh[64], dsh[64], cw[64], dw[64], bw[64];
    int t = threadIdx.x;

    if (t < 64) {
        float c = 0.f, d = 0.f;
        for (int i = 0; i < 64; i++) {
            float w = w2[i * 64 + t];
            c += w1[i] * w;
            d += b1[i] * w;
        }
        csh[t] = c; dsh[t] = d;
    }
    __syncthreads();

    if (t < 64) {
        float a = 0.f, b = 0.f, c = 0.f;
        for (int i = 0; i < 64; i++) {
            float w = attn_w[i * 64 + t];
            a += csh[i] * w;
            b += dsh[i] * w;
            c += b2[i]  * w;
        }
        cw[t] = a; dw[t] = b; bw[t] = c;
    }
    __syncthreads();

    if (t == 0) {
        float CT=0,DT=0,BT=0,CB=0,DB=0,BB=0;
        for (int j = 0; j < 64; j++) {
            float at = attn_a[j], ab = attn_a[64 + j];
            CT += cw[j]*at; DT += dw[j]*at; BT += bw[j]*at;
            CB += cw[j]*ab; DB += dw[j]*ab; BB += bw[j]*ab;
        }
        g_sc[0]=CT; g_sc[1]=DT; g_sc[2]=BT; g_sc[3]=CB; g_sc[4]=DB; g_sc[5]=BB;
    }

    // gc/gd/g0 for LSTM input projection, layout [gate*64+kout]
    {
        float a = 0.f, b = 0.f, c = 0.f;
        for (int k = 0; k < 64; k++) {
            float w = w_ih[t * 64 + k];
            a += w * csh[k];
            b += w * dsh[k];
            c += w * b2[k];
        }
        g_gc[t] = a;
        g_gd[t] = b;
        g_g0[t] = c + b_ih[t] + b_hh[t];
    }

    // B-fragments for mma.sync m16n8k16 (col-major B, k x n):
    // lane holds col = lane/4; reg r covers k rows kt*16 + r*8 + 2*(lane%4)+{0,1}
    // warp w, tile tau: column c (0..7) = kout_local -> w_hh row tau*64 + w*8 + c
    for (int idx = t; idx < 4096; idx += 256) {
        int lane = idx & 31;
        int kt   = (idx >> 5) & 3;
        int tau  = (idx >> 7) & 3;
        int w    = idx >> 9;
        int col  = lane >> 2;
        int nrow = tau * 64 + w * 8 + col;
        int k0   = kt * 16 + 2 * (lane & 3);
        const float* wr = w_hh + nrow * 64;
        float w0 = wr[k0],     w1 = wr[k0 + 1];
        float w8 = wr[k0 + 8], w9 = wr[k0 + 9];
        float h0 = __bfloat162float(__float2bfloat16_rn(w0));
        float h1 = __bfloat162float(__float2bfloat16_rn(w1));
        float h8 = __bfloat162float(__float2bfloat16_rn(w8));
        float h9 = __bfloat162float(__float2bfloat16_rn(w9));
        uint4 q;
        q.x = pack_bf2(w0, w1);
        q.y = pack_bf2(w8, w9);
        q.z = pack_bf2(w0 - h0, w1 - h1);
        q.w = pack_bf2(w8 - h8, w9 - h9);
        g_Bfrag[idx] = q;
    }
}

// ---------------------------------------------------------------------------
// Kernel 2: transpose inputs into F[v][n]  (n = branch*48 + b*12 + t)
// ---------------------------------------------------------------------------
__global__ void k_transpose(const float* __restrict__ ten, const float* __restrict__ per) {
    int i = blockIdx.x * 256 + threadIdx.x;   // < Vn*NN
    int v = i / NN, n = i % NN;
    const float* src = (n < 48) ? ten : per;
    int nl = n % 48;
    g_Ft[i] = src[nl * Vn + v];
}

// ---------------------------------------------------------------------------
// Kernel 3: vertex degree per hypergraph
// ---------------------------------------------------------------------------
__global__ void k_deg(const int* __restrict__ edges) {
    int i = blockIdx.x * 256 + threadIdx.x;   // < NH*ES
    int h = i / ES;
    atomicAdd(&g_degi[h * Vn + edges[i]], 1);
}

__global__ void k_rdeg() {
    int i = blockIdx.x * 256 + threadIdx.x;
    if (i < NH * Vn) {
        int dg = g_degi[i];
        g_rdeg[i] = 1.0f / (float)(dg > 0 ? dg : 1);
    }
}

// ---------------------------------------------------------------------------
// Kernel 4: a1[h][e][n] = mean_s F[edges[h,e,s]][n]   (float4 over n)
// ---------------------------------------------------------------------------
__global__ void k_gather_a1(const int* __restrict__ edges) {
    int i = blockIdx.x * 256 + threadIdx.x;   // < NH*NE*24
    int n4 = (i % 24) * 4;
    int e  = (i / 24) % NE;
    int h  = i / (24 * NE);
    const int* ep = edges + (h * NE + e) * NS;
    float4 acc = make_float4(0.f, 0.f, 0.f, 0.f);
    #pragma unroll
    for (int s = 0; s < NS; s++) {
        const float4 f = *(const float4*)&g_Ft[ep[s] * NN + n4];
        acc.x += f.x; acc.y += f.y; acc.z += f.z; acc.w += f.w;
    }
    const float r = 1.0f / NS;
    acc.x *= r; acc.y *= r; acc.z *= r; acc.w *= r;
    *(float4*)&g_a1[(h * NE + e) * NN + n4] = acc;
}

// ---------------------------------------------------------------------------
// Kernel 5: scatter a1 -> s1 raw sums (vectorized red.global.add.v4.f32)
// ---------------------------------------------------------------------------
__device__ __forceinline__ void red_v4(float* p, float4 v) {
    asm volatile("red.global.add.v4.f32 [%0], {%1, %2, %3, %4};"
                 :: "l"(p), "f"(v.x), "f"(v.y), "f"(v.z), "f"(v.w) : "memory");
}

__global__ void k_scatter_s1(const int* __restrict__ edges) {
    int i = blockIdx.x * 256 + threadIdx.x;   // < NH*ES*24
    int n4   = (i % 24) * 4;
    int slot = (i / 24) % ES;
    int h    = i / (24 * ES);
    int v = edges[h * ES + slot];
    int e = slot >> 5;
    float4 a = *(const float4*)&g_a1[(h * NE + e) * NN + n4];
    red_v4(&g_s1[(h * Vn + v) * NN + n4], a);
}

// ---------------------------------------------------------------------------
// Kernel 6: m1[h][e][n] = mean_s ( s1[edges]/deg )
// ---------------------------------------------------------------------------
__global__ void k_gather_m1(const int* __restrict__ edges) {
    int i = blockIdx.x * 256 + threadIdx.x;   // < NH*NE*24
    int n4 = (i % 24) * 4;
    int e  = (i / 24) % NE;
    int h  = i / (24 * NE);
    const int* ep = edges + (h * NE + e) * NS;
    float4 acc = make_float4(0.f, 0.f, 0.f, 0.f);
    #pragma unroll
    for (int s = 0; s < NS; s++) {
        int v = ep[s];
        float rd = g_rdeg[h * Vn + v];
        const float4 f = *(const float4*)&g_s1[(h * Vn + v) * NN + n4];
        acc.x += f.x * rd; acc.y += f.y * rd; acc.z += f.z * rd; acc.w += f.w * rd;
    }
    const float r = 1.0f / NS;
    acc.x *= r; acc.y *= r; acc.z *= r; acc.w *= r;
    *(float4*)&g_m1[(h * NE + e) * NN + n4] = acc;
}

// ---------------------------------------------------------------------------
// Kernel 7: scatter m1 -> traw
// ---------------------------------------------------------------------------
__global__ void k_scatter_t(const int* __restrict__ edges) {
    int i = blockIdx.x * 256 + threadIdx.x;   // < NH*ES*24
    int n4   = (i % 24) * 4;
    int slot = (i / 24) % ES;
    int h    = i / (24 * ES);
    int v = edges[h * ES + slot];
    int e = slot >> 5;
    float4 a = *(const float4*)&g_m1[(h * NE + e) * NN + n4];
    red_v4(&g_traw[(h * Vn + v) * NN + n4], a);
}

// ---------------------------------------------------------------------------
// Kernel 8: attention over H=3 (scalar form) -> T, P fields
// ---------------------------------------------------------------------------
__global__ void k_attn() {
    int i = blockIdx.x * 256 + threadIdx.x;   // < NN*Vn, layout [n][v]
    int v = i % Vn;
    int n = i / Vn;

    float CT = g_sc[0], DT = g_sc[1], BT = g_sc[2];
    float CB = g_sc[3], DB = g_sc[4], BB = g_sc[5];

    float tv[NH], uf[NH];
    #pragma unroll
    for (int h = 0; h < NH; h++) {
        int idx = h * Vn + v;
        int dg = g_degi[idx];
        uf[h] = (dg > 0) ? 1.0f : 0.0f;
        tv[h] = g_traw[idx * NN + n] * g_rdeg[idx];
    }
    float tbar = (tv[0] + tv[1] + tv[2]) * (1.0f / 3.0f);
    float usum = uf[0] + uf[1] + uf[2];
    float zc = CB * tbar + BB + usum * (1.0f / 3.0f) * DB;

    float z[NH];
    #pragma unroll
    for (int h = 0; h < NH; h++) {
        float zz = CT * tv[h] + uf[h] * DT + BT + zc;
        z[h] = (zz > 0.f) ? zz : 0.2f * zz;     // leaky_relu(0.2)
    }
    float m = fmaxf(z[0], fmaxf(z[1], z[2]));
    float e0 = __expf(z[0] - m), e1 = __expf(z[1] - m), e2 = __expf(z[2] - m);
    float rden = 1.0f / (e0 + e1 + e2);
    g_T[i] = (e0 * tv[0] + e1 * tv[1] + e2 * tv[2]) * rden;
    g_P[i] = (e0 * uf[0] + e1 * uf[1] + e2 * uf[2]) * rden;
}

// ---------------------------------------------------------------------------
// Kernel 9: warp-MMA LSTM. 64 sequences / CTA, 8 warps, grid 1250.
//
//  per step: gates(64x256 fp32 in D-frags) = h(64x64)@W_hh^T, via
//  mma.sync m16n8k16 bf16 3-pass hi/lo split, fp32 accumulate.
//  Warp w owns 32 gate-columns arranged as 4 n-tiles (tau = gate index),
//  in-tile column = kout_local, so each lane gets all 4 gates of
//  kouts w*8+2*(lane%4)+{0,1} for seq rows lane/4 (+8) of each m-tile.
//  h double-buffered in shared as bf16 hi/lo, 144B row stride (odd*16B
//  -> conflict-free ldmatrix). W fragments resident in registers.
// ---------------------------------------------------------------------------
#define HROW 144                      // bytes per h row (72 bf16)
#define HBUF_PART 9216                // 64 rows * 144
#define HBUF_BUF  18432               // hi + lo

__global__ void __launch_bounds__(256) k_lstm_mma(const float* __restrict__ w_out,
                                                  float* __restrict__ out) {
    __shared__ __align__(16) char hbuf[2 * HBUF_BUF];   // 36864 B
    __shared__ float Tsh[NTT * 64], Psh[NTT * 64];
    __shared__ float psum[64];

    const int tid  = threadIdx.x;
    const int wid  = tid >> 5;
    const int lane = tid & 31;
    const int sb   = blockIdx.x * 64;
    const int bo   = (sb >= 40000) ? 64 : 0;      // w_out branch offset
    const int m2   = lane & 3;
    const int kg0  = wid * 8 + 2 * m2;            // this lane's kout pair

    // ---- resident B fragments (64 regs) ----
    uint32_t Bh[4][4][2], Bl[4][4][2];
    #pragma unroll
    for (int tau = 0; tau < 4; tau++)
        #pragma unroll
        for (int kt = 0; kt < 4; kt++) {
            uint4 q = g_Bfrag[((wid * 4 + tau) * 4 + kt) * 32 + lane];
            Bh[tau][kt][0] = q.x; Bh[tau][kt][1] = q.y;
            Bl[tau][kt][0] = q.z; Bl[tau][kt][1] = q.w;
        }

    // ---- projection coefficients for this lane's 2 kouts x 4 gates ----
    float gcv[4][2], gdv[4][2], g0v[4][2];
    #pragma unroll
    for (int tau = 0; tau < 4; tau++) {
        gcv[tau][0] = g_gc[tau * 64 + kg0];     gcv[tau][1] = g_gc[tau * 64 + kg0 + 1];
        gdv[tau][0] = g_gd[tau * 64 + kg0];     gdv[tau][1] = g_gd[tau * 64 + kg0 + 1];
        g0v[tau][0] = g_g0[tau * 64 + kg0];     g0v[tau][1] = g_g0[tau * 64 + kg0 + 1];
    }
    const float wo0 = w_out[bo + kg0], wo1 = w_out[bo + kg0 + 1];

    // ---- T/P for this CTA's 64 seqs x 12 steps ----
    for (int idx = tid; idx < NTT * 64; idx += 256) {
        int s = idx & 63, tt = idx >> 6;
        int sq = sb + s;
        int branch = sq / 40000;
        int rem = sq - branch * 40000;
        int b = rem / Vn;
        int v = rem - b * Vn;
        int n = branch * 48 + b * 12 + tt;
        Tsh[tt * 64 + s] = g_T[n * Vn + v];
        Psh[tt * 64 + s] = g_P[n * Vn + v];
    }
    if (tid < 64) psum[tid] = 0.f;
    __syncthreads();

    const uint32_t hb32 = smem_u32(hbuf);
    // ldmatrix per-lane row address components
    const int grp   = lane >> 3;
    const int arow_local = ((grp & 1) << 3) + (lane & 7);   // row within 16-row tile
    const uint32_t acolb = (uint32_t)(grp >> 1) * 16;       // byte col (k half)

    float cst[4][2][2];                 // [mtile][rowhalf][e]
    #pragma unroll
    for (int a = 0; a < 4; a++)
        #pragma unroll
        for (int b = 0; b < 2; b++) { cst[a][b][0] = 0.f; cst[a][b][1] = 0.f; }

    for (int t = 0; t < NTT; t++) {
        const int rb = t & 1, wb = rb ^ 1;
        #pragma unroll
        for (int mt = 0; mt < 4; mt++) {
            const int r0 = mt * 16 + (lane >> 2);
            const float T0 = Tsh[t * 64 + r0],     P0 = Psh[t * 64 + r0];
            const float T1 = Tsh[t * 64 + r0 + 8], P1 = Psh[t * 64 + r0 + 8];

            float D[4][4];
            #pragma unroll
            for (int tau = 0; tau < 4; tau++) {
                D[tau][0] = fmaf(T0, gcv[tau][0], fmaf(P0, gdv[tau][0], g0v[tau][0]));
                D[tau][1] = fmaf(T0, gcv[tau][1], fmaf(P0, gdv[tau][1], g0v[tau][1]));
                D[tau][2] = fmaf(T1, gcv[tau][0], fmaf(P1, gdv[tau][0], g0v[tau][0]));
                D[tau][3] = fmaf(T1, gcv[tau][1], fmaf(P1, gdv[tau][1], g0v[tau][1]));
            }

            if (t > 0) {
                uint32_t Ah[4][4], Al[4][4];
                const uint32_t abase = hb32 + (uint32_t)rb * HBUF_BUF
                                     + (uint32_t)(mt * 16 + arow_local) * HROW + acolb;
                #pragma unroll
                for (int kt = 0; kt < 4; kt++) {
                    ldsm4(Ah[kt], abase + (uint32_t)kt * 32);
                    ldsm4(Al[kt], abase + HBUF_PART + (uint32_t)kt * 32);
                }
                #pragma unroll
                for (int tau = 0; tau < 4; tau++)
                    #pragma unroll
                    for (int kt = 0; kt < 4; kt++) {
                        mma_bf16(D[tau], Ah[kt], Bh[tau][kt]);
                        mma_bf16(D[tau], Al[kt], Bh[tau][kt]);
                        mma_bf16(D[tau], Ah[kt], Bl[tau][kt]);
                    }
            }

            // epilogue: 2 rows x 2 kouts per lane
            #pragma unroll
            for (int rh = 0; rh < 2; rh++) {
                float hv[2];
                #pragma unroll
                for (int e = 0; e < 2; e++) {
                    const int c = rh * 2 + e;
                    float gi = D[0][c], gf = D[1][c], gg = D[2][c], go = D[3][c];
                    float cn = sigm(gf) * cst[mt][rh][e] + sigm(gi) * tanh_e(gg);
                    cst[mt][rh][e] = cn;
                    hv[e] = sigm(go) * tanh_e(cn);
                }
                const int row = r0 + rh * 8;
                if (t == NTT - 1) {
                    atomicAdd(&psum[row], hv[0] * wo0 + hv[1] * wo1);
                } else {
                    __nv_bfloat16 b0 = __float2bfloat16_rn(hv[0]);
                    __nv_bfloat16 b1 = __float2bfloat16_rn(hv[1]);
                    __nv_bfloat162 ph = make_bfloat162(b0, b1);
                    __nv_bfloat162 pl = make_bfloat162(
                        __float2bfloat16_rn(hv[0] - __bfloat162float(b0)),
                        __float2bfloat16_rn(hv[1] - __bfloat162float(b1)));
                    char* dst = hbuf + wb * HBUF_BUF + row * HROW + kg0 * 2;
                    *(uint32_t*)dst               = *(uint32_t*)&ph;
                    *(uint32_t*)(dst + HBUF_PART) = *(uint32_t*)&pl;
                }
            }
        }
        __syncthreads();
    }

    if (tid < 64) {
        int rem = (sb + tid) % 40000;             // = b*V + v
        atomicAdd(&out[rem], psum[tid]);
    }
}

// ---------------------------------------------------------------------------
// Host launch
// ---------------------------------------------------------------------------
extern "C" void kernel_launch(void* const* d_in, const int* in_sizes, int n_in,
                              void* d_out, int out_size) {
    const float* tendency    = (const float*)d_in[0];
    const float* periodicity = (const float*)d_in[1];
    const int*   edges       = (const int*)  d_in[2];
    const float* w1          = (const float*)d_in[3];
    const float* b1          = (const float*)d_in[4];
    const float* w2          = (const float*)d_in[5];
    const float* b2          = (const float*)d_in[6];
    const float* attn_w      = (const float*)d_in[7];
    const float* attn_a      = (const float*)d_in[8];
    const float* w_ih        = (const float*)d_in[9];
    const float* w_hh        = (const float*)d_in[10];
    const float* b_ih        = (const float*)d_in[11];
    const float* b_hh        = (const float*)d_in[12];
    const float* w_out       = (const float*)d_in[13];
    const float* b_out       = (const float*)d_in[14];
    float* out = (float*)d_out;

    k_zero      <<<11250, 256>>>(out, b_out);
    k_prep      <<<1,     256>>>(w1, b1, w2, b2, attn_w, attn_a, w_ih, w_hh, b_ih, b_hh);
    k_transpose <<<3750,  256>>>(tendency, periodicity);
    k_deg       <<<(NH * ES) / 256, 256>>>(edges);            // 192 blocks
    k_rdeg      <<<(NH * Vn + 255) / 256, 256>>>();
    k_gather_a1 <<<(NH * NE * 24) / 256, 256>>>(edges);       // 144
    k_scatter_s1<<<(NH * ES * 24) / 256, 256>>>(edges);       // 4608
    k_gather_m1 <<<(NH * NE * 24) / 256, 256>>>(edges);
    k_scatter_t <<<(NH * ES * 24) / 256, 256>>>(edges);
    k_attn      <<<3750,  256>>>();
    k_lstm_mma  <<<1250,  256>>>(w_out, out);
}

// round 15
// speedup vs baseline: 4.4499x; 1.0002x over previous
#include <cuda_runtime.h>
#include <cuda_bf16.h>
#include <stdint.h>

// ---------------------------------------------------------------------------
// Problem constants
// ---------------------------------------------------------------------------
#define Vn   10000
#define NBAT 4
#define NTT  12
#define NN   96          // 2 branches * 4 * 12
#define NH   3
#define NE   512
#define NS   32
#define ES   (NE*NS)     // 16384

typedef unsigned long long u64;

// ---------------------------------------------------------------------------
// Device scratch (static allocation; no cudaMalloc allowed)
// ---------------------------------------------------------------------------
__device__ float g_Ft   [Vn * NN];        // transposed inputs F[v][n]
__device__ int   g_degi [NH * Vn];        // vertex degree per hypergraph
__device__ float g_rdeg [NH * Vn];        // 1 / max(deg,1)
__device__ float g_a1   [NH * NE * NN];   // layer-1 edge means
__device__ float g_s1   [NH * Vn * NN];   // layer-1 raw scatter sums
__device__ float g_m1   [NH * NE * NN];   // layer-2 edge means
__device__ float g_traw [NH * Vn * NN];   // layer-2 raw scatter sums
__device__ float g_T    [NN * Vn];        // attention-fused scalar field (t)
__device__ float g_P    [NN * Vn];        // attention-fused incidence field
__device__ float g_gc   [256];            // w_ih @ c   [gate*64+kout]
__device__ float g_gd   [256];            // w_ih @ d
__device__ float g_g0   [256];            // w_ih @ b2 + b_ih + b_hh
__device__ float g_sc   [6];              // CT, DT, BT, CB, DB, BB
// W_hh mma B-fragments, per-lane register layout:
// index ((w*4 + tau)*4 + kt)*32 + lane -> {bhi0, bhi1, blo0, blo1}
__device__ uint4 g_Bfrag[8 * 4 * 4 * 32];

// ---------------------------------------------------------------------------
// Math helpers (fp32, exp-based — proven 1e-7 accurate in R3)
// ---------------------------------------------------------------------------
__device__ __forceinline__ float sigm(float x) {
    float t = __expf(-x);
    return __fdividef(1.0f, 1.0f + t);
}
__device__ __forceinline__ float tanh_e(float x) {
    x = fminf(fmaxf(x, -8.0f), 8.0f);
    float t = __expf(2.0f * x);
    return __fdividef(t - 1.0f, t + 1.0f);
}

__device__ __forceinline__ uint32_t smem_u32(const void* p) {
    uint32_t a;
    asm("{ .reg .u64 t; cvta.to.shared.u64 t, %1; cvt.u32.u64 %0, t; }"
        : "=r"(a) : "l"(p));
    return a;
}

// classic warp-level bf16 MMA, fp32 accumulate (sm_80+, works on plain sm_103)
__device__ __forceinline__ void mma_bf16(float* d, const uint32_t* a, const uint32_t* b) {
    asm volatile("mma.sync.aligned.m16n8k16.row.col.f32.bf16.bf16.f32 "
        "{%0,%1,%2,%3}, {%4,%5,%6,%7}, {%8,%9}, {%0,%1,%2,%3};"
        : "+f"(d[0]), "+f"(d[1]), "+f"(d[2]), "+f"(d[3])
        : "r"(a[0]), "r"(a[1]), "r"(a[2]), "r"(a[3]), "r"(b[0]), "r"(b[1]));
}
__device__ __forceinline__ void ldsm4(uint32_t* r, uint32_t addr) {
    asm volatile("ldmatrix.sync.aligned.m8n8.x4.shared.b16 {%0,%1,%2,%3}, [%4];"
        : "=r"(r[0]), "=r"(r[1]), "=r"(r[2]), "=r"(r[3]) : "r"(addr));
}

// ---------------------------------------------------------------------------
// Kernel 0: zero scratch + init output to b_out
// ---------------------------------------------------------------------------
__global__ void k_zero(float* __restrict__ out, const float* __restrict__ b_out) {
    int i = blockIdx.x * 256 + threadIdx.x;   // grid covers NH*Vn*NN = 2,880,000
    g_s1[i]   = 0.f;
    g_traw[i] = 0.f;
    if (i < NH * Vn) g_degi[i] = 0;
    if (i < NBAT * Vn) out[i] = b_out[0];
}

// ---------------------------------------------------------------------------
// Kernel 1: precompute weight-derived constants (1 block, 256 threads)
// ---------------------------------------------------------------------------
__device__ __forceinline__ uint32_t pack_bf2(float a, float b) {
    __nv_bfloat162 p = make_bfloat162(__float2bfloat16_rn(a), __float2bfloat16_rn(b));
    return *(uint32_t*)&p;
}

__global__ void k_prep(const float* __restrict__ w1,     const float* __restrict__ b1,
                       const float* __restrict__ w2,     const float* __restrict__ b2,
                       const float* __restrict__ attn_w, const float* __restrict__ attn_a,
                       const float* __restrict__ w_ih,   const float* __restrict__ w_hh,
                       const float* __restrict__ b_ih,   const float* __restrict__ b_hh) {
    __shared__ float csh[64], dsh[64], cw[64], dw[64], bw[64];
    int t = threadIdx.x;

    if (t < 64) {
        float c = 0.f, d = 0.f;
        for (int i = 0; i < 64; i++) {
            float w = w2[i * 64 + t];
            c += w1[i] * w;
            d += b1[i] * w;
        }
        csh[t] = c; dsh[t] = d;
    }
    __syncthreads();

    if (t < 64) {
        float a = 0.f, b = 0.f, c = 0.f;
        for (int i = 0; i < 64; i++) {
            float w = attn_w[i * 64 + t];
            a += csh[i] * w;
            b += dsh[i] * w;
            c += b2[i]  * w;
        }
        cw[t] = a; dw[t] = b; bw[t] = c;
    }
    __syncthreads();

    if (t == 0) {
        float CT=0,DT=0,BT=0,CB=0,DB=0,BB=0;
        for (int j = 0; j < 64; j++) {
            float at = attn_a[j], ab = attn_a[64 + j];
            CT += cw[j]*at; DT += dw[j]*at; BT += bw[j]*at;
            CB += cw[j]*ab; DB += dw[j]*ab; BB += bw[j]*ab;
        }
        g_sc[0]=CT; g_sc[1]=DT; g_sc[2]=BT; g_sc[3]=CB; g_sc[4]=DB; g_sc[5]=BB;
    }

    // gc/gd/g0 for LSTM input projection, layout [gate*64+kout]
    {
        float a = 0.f, b = 0.f, c = 0.f;
        for (int k = 0; k < 64; k++) {
            float w = w_ih[t * 64 + k];
            a += w * csh[k];
            b += w * dsh[k];
            c += w * b2[k];
        }
        g_gc[t] = a;
        g_gd[t] = b;
        g_g0[t] = c + b_ih[t] + b_hh[t];
    }

    // B-fragments for mma.sync m16n8k16 (col-major B, k x n):
    // lane holds col = lane/4; reg r covers k rows kt*16 + r*8 + 2*(lane%4)+{0,1}
    // warp w, tile tau: column c (0..7) = kout_local -> w_hh row tau*64 + w*8 + c
    for (int idx = t; idx < 4096; idx += 256) {
        int lane = idx & 31;
        int kt   = (idx >> 5) & 3;
        int tau  = (idx >> 7) & 3;
        int w    = idx >> 9;
        int col  = lane >> 2;
        int nrow = tau * 64 + w * 8 + col;
        int k0   = kt * 16 + 2 * (lane & 3);
        const float* wr = w_hh + nrow * 64;
        float w0 = wr[k0],     w1 = wr[k0 + 1];
        float w8 = wr[k0 + 8], w9 = wr[k0 + 9];
        float h0 = __bfloat162float(__float2bfloat16_rn(w0));
        float h1 = __bfloat162float(__float2bfloat16_rn(w1));
        float h8 = __bfloat162float(__float2bfloat16_rn(w8));
        float h9 = __bfloat162float(__float2bfloat16_rn(w9));
        uint4 q;
        q.x = pack_bf2(w0, w1);
        q.y = pack_bf2(w8, w9);
        q.z = pack_bf2(w0 - h0, w1 - h1);
        q.w = pack_bf2(w8 - h8, w9 - h9);
        g_Bfrag[idx] = q;
    }
}

// ---------------------------------------------------------------------------
// Kernel 2: transpose inputs into F[v][n]  (n = branch*48 + b*12 + t)
// ---------------------------------------------------------------------------
__global__ void k_transpose(const float* __restrict__ ten, const float* __restrict__ per) {
    int i = blockIdx.x * 256 + threadIdx.x;   // < Vn*NN
    int v = i / NN, n = i % NN;
    const float* src = (n < 48) ? ten : per;
    int nl = n % 48;
    g_Ft[i] = src[nl * Vn + v];
}

// ---------------------------------------------------------------------------
// Kernel 3: vertex degree per hypergraph
// ---------------------------------------------------------------------------
__global__ void k_deg(const int* __restrict__ edges) {
    int i = blockIdx.x * 256 + threadIdx.x;   // < NH*ES
    int h = i / ES;
    atomicAdd(&g_degi[h * Vn + edges[i]], 1);
}

__global__ void k_rdeg() {
    int i = blockIdx.x * 256 + threadIdx.x;
    if (i < NH * Vn) {
        int dg = g_degi[i];
        g_rdeg[i] = 1.0f / (float)(dg > 0 ? dg : 1);
    }
}

// ---------------------------------------------------------------------------
// Kernel 4: a1[h][e][n] = mean_s F[edges[h,e,s]][n]   (float4 over n)
// ---------------------------------------------------------------------------
__global__ void k_gather_a1(const int* __restrict__ edges) {
    int i = blockIdx.x * 256 + threadIdx.x;   // < NH*NE*24
    int n4 = (i % 24) * 4;
    int e  = (i / 24) % NE;
    int h  = i / (24 * NE);
    const int* ep = edges + (h * NE + e) * NS;
    float4 acc = make_float4(0.f, 0.f, 0.f, 0.f);
    #pragma unroll
    for (int s = 0; s < NS; s++) {
        const float4 f = *(const float4*)&g_Ft[ep[s] * NN + n4];
        acc.x += f.x; acc.y += f.y; acc.z += f.z; acc.w += f.w;
    }
    const float r = 1.0f / NS;
    acc.x *= r; acc.y *= r; acc.z *= r; acc.w *= r;
    *(float4*)&g_a1[(h * NE + e) * NN + n4] = acc;
}

// ---------------------------------------------------------------------------
// Kernel 5: scatter a1 -> s1 raw sums (vectorized red.global.add.v4.f32)
// ---------------------------------------------------------------------------
__device__ __forceinline__ void red_v4(float* p, float4 v) {
    asm volatile("red.global.add.v4.f32 [%0], {%1, %2, %3, %4};"
                 :: "l"(p), "f"(v.x), "f"(v.y), "f"(v.z), "f"(v.w) : "memory");
}

__global__ void k_scatter_s1(const int* __restrict__ edges) {
    int i = blockIdx.x * 256 + threadIdx.x;   // < NH*ES*24
    int n4   = (i % 24) * 4;
    int slot = (i / 24) % ES;
    int h    = i / (24 * ES);
    int v = edges[h * ES + slot];
    int e = slot >> 5;
    float4 a = *(const float4*)&g_a1[(h * NE + e) * NN + n4];
    red_v4(&g_s1[(h * Vn + v) * NN + n4], a);
}

// ---------------------------------------------------------------------------
// Kernel 6: m1[h][e][n] = mean_s ( s1[edges]/deg )
// ---------------------------------------------------------------------------
__global__ void k_gather_m1(const int* __restrict__ edges) {
    int i = blockIdx.x * 256 + threadIdx.x;   // < NH*NE*24
    int n4 = (i % 24) * 4;
    int e  = (i / 24) % NE;
    int h  = i / (24 * NE);
    const int* ep = edges + (h * NE + e) * NS;
    float4 acc = make_float4(0.f, 0.f, 0.f, 0.f);
    #pragma unroll
    for (int s = 0; s < NS; s++) {
        int v = ep[s];
        float rd = g_rdeg[h * Vn + v];
        const float4 f = *(const float4*)&g_s1[(h * Vn + v) * NN + n4];
        acc.x += f.x * rd; acc.y += f.y * rd; acc.z += f.z * rd; acc.w += f.w * rd;
    }
    const float r = 1.0f / NS;
    acc.x *= r; acc.y *= r; acc.z *= r; acc.w *= r;
    *(float4*)&g_m1[(h * NE + e) * NN + n4] = acc;
}

// ---------------------------------------------------------------------------
// Kernel 7: scatter m1 -> traw
// ---------------------------------------------------------------------------
__global__ void k_scatter_t(const int* __restrict__ edges) {
    int i = blockIdx.x * 256 + threadIdx.x;   // < NH*ES*24
    int n4   = (i % 24) * 4;
    int slot = (i / 24) % ES;
    int h    = i / (24 * ES);
    int v = edges[h * ES + slot];
    int e = slot >> 5;
    float4 a = *(const float4*)&g_m1[(h * NE + e) * NN + n4];
    red_v4(&g_traw[(h * Vn + v) * NN + n4], a);
}

// ---------------------------------------------------------------------------
// Kernel 8: attention over H=3 (scalar form) -> T, P fields
// ---------------------------------------------------------------------------
__global__ void k_attn() {
    int i = blockIdx.x * 256 + threadIdx.x;   // < NN*Vn, layout [n][v]
    int v = i % Vn;
    int n = i / Vn;

    float CT = g_sc[0], DT = g_sc[1], BT = g_sc[2];
    float CB = g_sc[3], DB = g_sc[4], BB = g_sc[5];

    float tv[NH], uf[NH];
    #pragma unroll
    for (int h = 0; h < NH; h++) {
        int idx = h * Vn + v;
        int dg = g_degi[idx];
        uf[h] = (dg > 0) ? 1.0f : 0.0f;
        tv[h] = g_traw[idx * NN + n] * g_rdeg[idx];
    }
    float tbar = (tv[0] + tv[1] + tv[2]) * (1.0f / 3.0f);
    float usum = uf[0] + uf[1] + uf[2];
    float zc = CB * tbar + BB + usum * (1.0f / 3.0f) * DB;

    float z[NH];
    #pragma unroll
    for (int h = 0; h < NH; h++) {
        float zz = CT * tv[h] + uf[h] * DT + BT + zc;
        z[h] = (zz > 0.f) ? zz : 0.2f * zz;     // leaky_relu(0.2)
    }
    float m = fmaxf(z[0], fmaxf(z[1], z[2]));
    float e0 = __expf(z[0] - m), e1 = __expf(z[1] - m), e2 = __expf(z[2] - m);
    float rden = 1.0f / (e0 + e1 + e2);
    g_T[i] = (e0 * tv[0] + e1 * tv[1] + e2 * tv[2]) * rden;
    g_P[i] = (e0 * uf[0] + e1 * uf[1] + e2 * uf[2]) * rden;
}

// ---------------------------------------------------------------------------
// Kernel 9: warp-MMA LSTM. 64 sequences / CTA, 8 warps, grid 1250.
//
//  per step: gates(64x256 fp32 in D-frags) = h(64x64)@W_hh^T, via
//  mma.sync m16n8k16 bf16 3-pass hi/lo split, fp32 accumulate.
//  Warp w owns 32 gate-columns arranged as 4 n-tiles (tau = gate index),
//  in-tile column = kout_local, so each lane gets all 4 gates of
//  kouts w*8+2*(lane%4)+{0,1} for seq rows lane/4 (+8) of each m-tile.
//  h double-buffered in shared as bf16 hi/lo, 144B row stride (odd*16B
//  -> conflict-free ldmatrix). W fragments resident in registers.
// ---------------------------------------------------------------------------
#define HROW 144                      // bytes per h row (72 bf16)
#define HBUF_PART 9216                // 64 rows * 144
#define HBUF_BUF  18432               // hi + lo

__global__ void __launch_bounds__(256) k_lstm_mma(const float* __restrict__ w_out,
                                                  float* __restrict__ out) {
    __shared__ __align__(16) char hbuf[2 * HBUF_BUF];   // 36864 B
    __shared__ float Tsh[NTT * 64], Psh[NTT * 64];
    __shared__ float psum[64];

    const int tid  = threadIdx.x;
    const int wid  = tid >> 5;
    const int lane = tid & 31;
    const int sb   = blockIdx.x * 64;
    const int bo   = (sb >= 40000) ? 64 : 0;      // w_out branch offset
    const int m2   = lane & 3;
    const int kg0  = wid * 8 + 2 * m2;            // this lane's kout pair

    // ---- resident B fragments (64 regs) ----
    uint32_t Bh[4][4][2], Bl[4][4][2];
    #pragma unroll
    for (int tau = 0; tau < 4; tau++)
        #pragma unroll
        for (int kt = 0; kt < 4; kt++) {
            uint4 q = g_Bfrag[((wid * 4 + tau) * 4 + kt) * 32 + lane];
            Bh[tau][kt][0] = q.x; Bh[tau][kt][1] = q.y;
            Bl[tau][kt][0] = q.z; Bl[tau][kt][1] = q.w;
        }

    // ---- projection coefficients for this lane's 2 kouts x 4 gates ----
    float gcv[4][2], gdv[4][2], g0v[4][2];
    #pragma unroll
    for (int tau = 0; tau < 4; tau++) {
        gcv[tau][0] = g_gc[tau * 64 + kg0];     gcv[tau][1] = g_gc[tau * 64 + kg0 + 1];
        gdv[tau][0] = g_gd[tau * 64 + kg0];     gdv[tau][1] = g_gd[tau * 64 + kg0 + 1];
        g0v[tau][0] = g_g0[tau * 64 + kg0];     g0v[tau][1] = g_g0[tau * 64 + kg0 + 1];
    }
    const float wo0 = w_out[bo + kg0], wo1 = w_out[bo + kg0 + 1];

    // ---- T/P for this CTA's 64 seqs x 12 steps ----
    for (int idx = tid; idx < NTT * 64; idx += 256) {
        int s = idx & 63, tt = idx >> 6;
        int sq = sb + s;
        int branch = sq / 40000;
        int rem = sq - branch * 40000;
        int b = rem / Vn;
        int v = rem - b * Vn;
        int n = branch * 48 + b * 12 + tt;
        Tsh[tt * 64 + s] = g_T[n * Vn + v];
        Psh[tt * 64 + s] = g_P[n * Vn + v];
    }
    if (tid < 64) psum[tid] = 0.f;
    __syncthreads();

    const uint32_t hb32 = smem_u32(hbuf);
    // ldmatrix per-lane row address components
    const int grp   = lane >> 3;
    const int arow_local = ((grp & 1) << 3) + (lane & 7);   // row within 16-row tile
    const uint32_t acolb = (uint32_t)(grp >> 1) * 16;       // byte col (k half)

    float cst[4][2][2];                 // [mtile][rowhalf][e]
    #pragma unroll
    for (int a = 0; a < 4; a++)
        #pragma unroll
        for (int b = 0; b < 2; b++) { cst[a][b][0] = 0.f; cst[a][b][1] = 0.f; }

    for (int t = 0; t < NTT; t++) {
        const int rb = t & 1, wb = rb ^ 1;
        #pragma unroll
        for (int mt = 0; mt < 4; mt++) {
            const int r0 = mt * 16 + (lane >> 2);
            const float T0 = Tsh[t * 64 + r0],     P0 = Psh[t * 64 + r0];
            const float T1 = Tsh[t * 64 + r0 + 8], P1 = Psh[t * 64 + r0 + 8];

            float D[4][4];
            #pragma unroll
            for (int tau = 0; tau < 4; tau++) {
                D[tau][0] = fmaf(T0, gcv[tau][0], fmaf(P0, gdv[tau][0], g0v[tau][0]));
                D[tau][1] = fmaf(T0, gcv[tau][1], fmaf(P0, gdv[tau][1], g0v[tau][1]));
                D[tau][2] = fmaf(T1, gcv[tau][0], fmaf(P1, gdv[tau][0], g0v[tau][0]));
                D[tau][3] = fmaf(T1, gcv[tau][1], fmaf(P1, gdv[tau][1], g0v[tau][1]));
            }

            if (t > 0) {
                uint32_t Ah[4][4], Al[4][4];
                const uint32_t abase = hb32 + (uint32_t)rb * HBUF_BUF
                                     + (uint32_t)(mt * 16 + arow_local) * HROW + acolb;
                #pragma unroll
                for (int kt = 0; kt < 4; kt++) {
                    ldsm4(Ah[kt], abase + (uint32_t)kt * 32);
                    ldsm4(Al[kt], abase + HBUF_PART + (uint32_t)kt * 32);
                }
                #pragma unroll
                for (int tau = 0; tau < 4; tau++)
                    #pragma unroll
                    for (int kt = 0; kt < 4; kt++) {
                        mma_bf16(D[tau], Ah[kt], Bh[tau][kt]);
                        mma_bf16(D[tau], Al[kt], Bh[tau][kt]);
                        mma_bf16(D[tau], Ah[kt], Bl[tau][kt]);
                    }
            }

            // epilogue: 2 rows x 2 kouts per lane
            #pragma unroll
            for (int rh = 0; rh < 2; rh++) {
                float hv[2];
                #pragma unroll
                for (int e = 0; e < 2; e++) {
                    const int c = rh * 2 + e;
                    float gi = D[0][c], gf = D[1][c], gg = D[2][c], go = D[3][c];
                    float cn = sigm(gf) * cst[mt][rh][e] + sigm(gi) * tanh_e(gg);
                    cst[mt][rh][e] = cn;
                    hv[e] = sigm(go) * tanh_e(cn);
                }
                const int row = r0 + rh * 8;
                if (t == NTT - 1) {
                    atomicAdd(&psum[row], hv[0] * wo0 + hv[1] * wo1);
                } else {
                    __nv_bfloat16 b0 = __float2bfloat16_rn(hv[0]);
                    __nv_bfloat16 b1 = __float2bfloat16_rn(hv[1]);
                    __nv_bfloat162 ph = make_bfloat162(b0, b1);
                    __nv_bfloat162 pl = make_bfloat162(
                        __float2bfloat16_rn(hv[0] - __bfloat162float(b0)),
                        __float2bfloat16_rn(hv[1] - __bfloat162float(b1)));
                    char* dst = hbuf + wb * HBUF_BUF + row * HROW + kg0 * 2;
                    *(uint32_t*)dst               = *(uint32_t*)&ph;
                    *(uint32_t*)(dst + HBUF_PART) = *(uint32_t*)&pl;
                }
            }
        }
        __syncthreads();
    }

    if (tid < 64) {
        int rem = (sb + tid) % 40000;             // = b*V + v
        atomicAdd(&out[rem], psum[tid]);
    }
}

// ---------------------------------------------------------------------------
// Host launch
// ---------------------------------------------------------------------------
extern "C" void kernel_launch(void* const* d_in, const int* in_sizes, int n_in,
                              void* d_out, int out_size) {
    const float* tendency    = (const float*)d_in[0];
    const float* periodicity = (const float*)d_in[1];
    const int*   edges       = (const int*)  d_in[2];
    const float* w1          = (const float*)d_in[3];
    const float* b1          = (const float*)d_in[4];
    const float* w2          = (const float*)d_in[5];
    const float* b2          = (const float*)d_in[6];
    const float* attn_w      = (const float*)d_in[7];
    const float* attn_a      = (const float*)d_in[8];
    const float* w_ih        = (const float*)d_in[9];
    const float* w_hh        = (const float*)d_in[10];
    const float* b_ih        = (const float*)d_in[11];
    const float* b_hh        = (const float*)d_in[12];
    const float* w_out       = (const float*)d_in[13];
    const float* b_out       = (const float*)d_in[14];
    float* out = (float*)d_out;

    k_zero      <<<11250, 256>>>(out, b_out);
    k_prep      <<<1,     256>>>(w1, b1, w2, b2, attn_w, attn_a, w_ih, w_hh, b_ih, b_hh);
    k_transpose <<<3750,  256>>>(tendency, periodicity);
    k_deg       <<<(NH * ES) / 256, 256>>>(edges);            // 192 blocks
    k_rdeg      <<<(NH * Vn + 255) / 256, 256>>>();
    k_gather_a1 <<<(NH * NE * 24) / 256, 256>>>(edges);       // 144
    k_scatter_s1<<<(NH * ES * 24) / 256, 256>>>(edges);       // 4608
    k_gather_m1 <<<(NH * NE * 24) / 256, 256>>>(edges);
    k_scatter_t <<<(NH * ES * 24) / 256, 256>>>(edges);
    k_attn      <<<3750,  256>>>();
    k_lstm_mma  <<<1250,  256>>>(w_out, out);
}